// round 11
// baseline (speedup 1.0000x reference)
#include <cuda_runtime.h>
#include <cuda_bf16.h>
#include <cstdint>

// ---------------- problem constants ----------------
#define BSZ   64
#define CC    2048
#define LL    192
#define DIN2  384
#define DD    192
#define NN    16
#define RR    6
#define MM    (BSZ*LL)     // 12288
#define NPROJ 38
#define DDP   256          // DD padded to BK multiple for int8 segments
#define KQ_C  (3*CC)       // 6144 int8 bytes (K' for C=2048 operands)
#define KQ_D  (3*DDP)      // 768 int8 bytes  (K' for D=192 operands, padded)

// ---------------- scratch ----------------
__device__ float g_fm32 [(size_t)MM*CC];    // LN output fp32
__device__ float g_out132[(size_t)MM*CC];   // out-proj + resid fp32
__device__ float g_xz  [(size_t)MM*DIN2];
__device__ float g_xdbl[(size_t)MM*NPROJ];
__device__ float g_dts [(size_t)MM*DD];
__device__ float g_ssm [(size_t)MM*DD];     // scan gated output fp32
// quantized operands + per-row scales
__device__ __align__(128) int8_t g_fmq  [(size_t)MM*KQ_C];
__device__ __align__(128) int8_t g_out1q[(size_t)MM*KQ_C];
__device__ __align__(128) int8_t g_ssmq [(size_t)MM*KQ_D];
__device__ __align__(128) int8_t g_inwq [(size_t)DIN2*KQ_C];
__device__ __align__(128) int8_t g_outwq[(size_t)CC*KQ_D];
__device__ __align__(128) int8_t g_mowq [(size_t)CC*KQ_C];
__device__ float g_fms [MM];
__device__ float g_out1s[MM];
__device__ float g_ssms[MM];
__device__ float g_inws[DIN2];
__device__ float g_outws[CC];
__device__ float g_mows[CC];

// ---------------- helpers ----------------
__device__ __forceinline__ uint32_t smem_to_u32(const void* p) {
    uint32_t a;
    asm("{ .reg .u64 t; cvta.to.shared.u64 t, %1; cvt.u32.u64 %0, t; }" : "=r"(a) : "l"(p));
    return a;
}
#define SMEM_SWIZZLE_128B(off) ((off) ^ (((off) >> 3) & 0x70))

__device__ __forceinline__ uint32_t lds32(uint32_t a) {
    uint32_t v;
    asm volatile("ld.shared.b32 %0, [%1];" : "=r"(v) : "r"(a));
    return v;
}

#define CP_ASYNC16(smem_u32, gptr) \
    asm volatile("cp.async.cg.shared.global [%0], [%1], 16;" \
                 :: "r"(smem_u32), "l"(__cvta_generic_to_global((const void*)(gptr))) : "memory")
#define CP_ASYNC_COMMIT() asm volatile("cp.async.commit_group;" ::: "memory")
#define CP_ASYNC_WAIT_2() asm volatile("cp.async.wait_group 2;" ::: "memory")

// int8 mma: D(s32) = A(s8,16x32) * B(s8,32x8) + C
#define MMA_S8(d, a, b0, b1) \
    asm volatile("mma.sync.aligned.m16n8k32.row.col.s32.s8.s8.s32 " \
                 "{%0,%1,%2,%3}, {%4,%5,%6,%7}, {%8,%9}, {%0,%1,%2,%3};" \
                 : "+r"((d)[0]), "+r"((d)[1]), "+r"((d)[2]), "+r"((d)[3]) \
                 : "r"((a)[0]), "r"((a)[1]), "r"((a)[2]), "r"((a)[3]), \
                   "r"(b0), "r"(b1))

// ---------------- 1. transpose + LayerNorm -> fp32 fm ----------------
__global__ void ln_kernel(const float* __restrict__ x,
                          const float* __restrict__ w,
                          const float* __restrict__ b)
{
    int m  = blockIdx.x;
    int bb = m / LL, l = m % LL;
    const float* src = x + (size_t)bb * CC * LL + l;

    float v[8];
    float s = 0.f, s2 = 0.f;
#pragma unroll
    for (int k = 0; k < 8; k++) {
        int c = threadIdx.x + k * 256;
        float t = src[(size_t)c * LL];
        v[k] = t; s += t; s2 += t * t;
    }
    __shared__ float sred[64];
#pragma unroll
    for (int o = 16; o > 0; o >>= 1) {
        s  += __shfl_down_sync(0xffffffffu, s,  o);
        s2 += __shfl_down_sync(0xffffffffu, s2, o);
    }
    int wid = threadIdx.x >> 5, lane = threadIdx.x & 31;
    if (lane == 0) { sred[wid] = s; sred[32 + wid] = s2; }
    __syncthreads();
    if (threadIdx.x == 0) {
        float a = 0.f, a2 = 0.f;
#pragma unroll
        for (int i = 0; i < 8; i++) { a += sred[i]; a2 += sred[32 + i]; }
        sred[0] = a; sred[32] = a2;
    }
    __syncthreads();
    s = sred[0]; s2 = sred[32];

    float mu   = s * (1.f / CC);
    float var  = s2 * (1.f / CC) - mu * mu;
    float rstd = rsqrtf(var + 1e-5f);

    float* dst = g_fm32 + (size_t)m * CC;
#pragma unroll
    for (int k = 0; k < 8; k++) {
        int c = threadIdx.x + k * 256;
        dst[c] = (v[k] - mu) * rstd * w[c] + b[c];
    }
}

// ---------------- quantize: fp32 row -> 2-slice int8, 3 segments ----------------
// MODE 0 (activation): [a1 | a2 | a1]   MODE 1 (weight): [w1 | w1 | w2]
// v = S * (a1 + a2/254),  S = rowmax/127
template <int MODE>
__global__ void quant_kernel(const float* __restrict__ src, int8_t* __restrict__ dst,
                             float* __restrict__ scl, int K, int Kpad, int rows)
{
    int warp = (blockIdx.x * blockDim.x + threadIdx.x) >> 5;
    int lane = threadIdx.x & 31;
    if (warp >= rows) return;
    const float* r = src + (size_t)warp * K;
    int8_t* d = dst + (size_t)warp * 3 * Kpad;

    float mx = 0.f;
    for (int c = lane; c < K; c += 32) mx = fmaxf(mx, fabsf(r[c]));
#pragma unroll
    for (int o = 16; o > 0; o >>= 1) mx = fmaxf(mx, __shfl_xor_sync(0xffffffffu, mx, o));
    float S = fmaxf(mx, 1e-30f) * (1.f / 127.f);
    if (lane == 0) scl[warp] = S;
    float inv = 1.f / S;

    for (int c = lane; c < K; c += 32) {
        float u  = r[c] * inv;
        float a1 = rintf(u);
        float a2 = rintf((u - a1) * 254.f);
        int8_t q1 = (int8_t)(int)a1, q2 = (int8_t)(int)a2;
        if (MODE == 0) { d[c] = q1; d[Kpad + c] = q2; d[2 * Kpad + c] = q1; }
        else           { d[c] = q1; d[Kpad + c] = q1; d[2 * Kpad + c] = q2; }
    }
    for (int c = K + lane; c < Kpad; c += 32) {
        d[c] = 0; d[Kpad + c] = 0; d[2 * Kpad + c] = 0;
    }
}

// ---------------- int8 GEMM: C = Sa*Sw*( seg0 + (seg1+seg2)/254 ) ----------------
// 128x128 tile, BK=128 int8, 4-stage cp.async (distance 2, single sync),
// 8 warps (2m x 4n), warp tile 64x32, lds32 fragments.
// EPI 0: +bias -> xz fp32      EPI 1: +bias +fm32 resid -> out1 fp32
// EPI 2: +bias, BN, ReLU, NCHW -> out
template <int EPI>
__global__ void __launch_bounds__(256) gemm_s8(
    const int8_t* __restrict__ A, const int8_t* __restrict__ B,
    const float* __restrict__ SclA, const float* __restrict__ SclB,
    int Kq, int s0, int Nout,
    const float* __restrict__ bias, const float* __restrict__ resid,
    float* __restrict__ Cf,
    const float* __restrict__ bn_rm, const float* __restrict__ bn_rv,
    const float* __restrict__ bn_w,  const float* __restrict__ bn_b)
{
    constexpr int S      = 4;
    constexpr int ABYTES = 128 * 128;       // 128 rows x 128 int8
    constexpr int STAGE  = 2 * ABYTES;

    extern __shared__ char smem[];
    uint32_t sb = smem_to_u32(smem);

    int tid = threadIdx.x, wid = tid >> 5, lane = tid & 31;
    int m0 = blockIdx.y * 128, n0 = blockIdx.x * 128;
    int wm0 = (wid & 1) * 64;
    int wn0 = (wid >> 1) * 32;

    int r4 = lane >> 2;                     // fragment row/col group
    int kb = (lane & 3) * 4;                // byte offset of this thread's k-quad

    int acc0[4][4][4], acc1[4][4][4];
#pragma unroll
    for (int i = 0; i < 4; i++)
#pragma unroll
        for (int j = 0; j < 4; j++)
#pragma unroll
            for (int q = 0; q < 4; q++) { acc0[i][j][q] = 0; acc1[i][j][q] = 0; }

    const int T = Kq / 128;

    int lrow = tid >> 3;                    // 0..31
    int lcol = tid & 7;                     // 16B chunk col
    auto load = [&](int j) {
        uint32_t abase = sb + (j % S) * STAGE;
        uint32_t bbase = abase + ABYTES;
        int k0 = j * 128;
#pragma unroll
        for (int c = 0; c < 4; c++) {
            int row = lrow + c * 32;
            uint32_t soff = SMEM_SWIZZLE_128B((uint32_t)(row * 128 + lcol * 16));
            CP_ASYNC16(abase + soff, A + (size_t)(m0 + row) * Kq + k0 + lcol * 16);
            CP_ASYNC16(bbase + soff, B + (size_t)(n0 + row) * Kq + k0 + lcol * 16);
        }
    };

    auto compute = [&](int (&acc)[4][4][4], uint32_t abase, uint32_t bbase) {
#pragma unroll
        for (int kk = 0; kk < 4; kk++) {
            int kbyte = kk * 32 + kb;
            uint32_t a[4][4], bf[4][2];
#pragma unroll
            for (int mi = 0; mi < 4; mi++) {
                int r = wm0 + mi * 16 + r4;
                a[mi][0] = lds32(abase + SMEM_SWIZZLE_128B((uint32_t)(r * 128 + kbyte)));
                a[mi][1] = lds32(abase + SMEM_SWIZZLE_128B((uint32_t)((r + 8) * 128 + kbyte)));
                a[mi][2] = lds32(abase + SMEM_SWIZZLE_128B((uint32_t)(r * 128 + kbyte + 16)));
                a[mi][3] = lds32(abase + SMEM_SWIZZLE_128B((uint32_t)((r + 8) * 128 + kbyte + 16)));
            }
#pragma unroll
            for (int ni = 0; ni < 4; ni++) {
                int n = wn0 + ni * 8 + r4;
                bf[ni][0] = lds32(bbase + SMEM_SWIZZLE_128B((uint32_t)(n * 128 + kbyte)));
                bf[ni][1] = lds32(bbase + SMEM_SWIZZLE_128B((uint32_t)(n * 128 + kbyte + 16)));
            }
#pragma unroll
            for (int mi = 0; mi < 4; mi++)
#pragma unroll
                for (int ni = 0; ni < 4; ni++)
                    MMA_S8(acc[mi][ni], a[mi], bf[ni][0], bf[ni][1]);
        }
    };

    load(0); CP_ASYNC_COMMIT();
    load(1); CP_ASYNC_COMMIT();

    for (int i = 0; i < T; i++) {
        if (i + 2 < T) load(i + 2);
        CP_ASYNC_COMMIT();
        CP_ASYNC_WAIT_2();
        __syncthreads();
        // S=4, distance 2, single barrier: writes hit (i+2)%4, reads i%4 -> disjoint.
        uint32_t abase = sb + (i % S) * STAGE;
        uint32_t bbase = abase + ABYTES;
        if (i < s0) compute(acc0, abase, bbase);
        else        compute(acc1, abase, bbase);
    }

    // ---------------- epilogue ----------------
    int qrow = lane >> 2;
    int qcol = (lane & 3) * 2;
#pragma unroll
    for (int mi = 0; mi < 4; mi++) {
#pragma unroll
        for (int h = 0; h < 2; h++) {
            int m = m0 + wm0 + mi * 16 + qrow + h * 8;
            float sa = SclA[m];
#pragma unroll
            for (int ni = 0; ni < 4; ni++) {
#pragma unroll
                for (int q = 0; q < 2; q++) {
                    int n = n0 + wn0 + ni * 8 + qcol + q;
                    float sw = SclB[n];
                    float v = sa * sw * ((float)acc0[mi][ni][h * 2 + q]
                             + (float)acc1[mi][ni][h * 2 + q] * (1.f / 254.f));
                    v += bias[n];
                    if (EPI == 0) {
                        Cf[(size_t)m * Nout + n] = v;
                    } else if (EPI == 1) {
                        Cf[(size_t)m * CC + n] = v + resid[(size_t)m * CC + n];
                    } else {
                        float rs = rsqrtf(bn_rv[n] + 1e-5f);
                        v = (v - bn_rm[n]) * rs * bn_w[n] + bn_b[n];
                        v = fmaxf(v, 0.f);
                        int bb = m / LL, l = m - bb * LL;
                        Cf[((size_t)bb * CC + n) * LL + l] = v;
                    }
                }
            }
        }
    }
}

// ---------------- x_proj ----------------
__global__ void xproj_kernel(const float* __restrict__ xpw)
{
    int idx = blockIdx.x * blockDim.x + threadIdx.x;
    if (idx >= MM * NPROJ) return;
    int m = idx / NPROJ, j = idx % NPROJ;
    const float* xr = g_xz + (size_t)m * DIN2;
    const float* wr = xpw + j * DD;
    float acc = 0.f;
#pragma unroll 8
    for (int k = 0; k < DD; k++) acc += xr[k] * wr[k];
    g_xdbl[idx] = acc;
}

// ---------------- dt softplus ----------------
__global__ void dt_kernel(const float* __restrict__ dtw)
{
    int idx = blockIdx.x * blockDim.x + threadIdx.x;
    if (idx >= MM * DD) return;
    int m = idx / DD, d = idx % DD;
    const float* xd = g_xdbl + (size_t)m * NPROJ;
    float acc = 0.f;
#pragma unroll
    for (int r = 0; r < RR; r++) acc += xd[r] * dtw[d * RR + r];
    float sp = (acc > 20.f) ? acc : log1pf(__expf(acc));
    g_dts[idx] = sp;
}

// ---------------- bidirectional scan + SiLU gate -> fp32 ssm ----------------
__global__ void scan_kernel(const float* __restrict__ A_logs,
                            const float* __restrict__ Ds)
{
    __shared__ float sB[LL][NN];
    __shared__ float sC[LL][NN];
    int b = blockIdx.x, d = threadIdx.x;

    for (int i = d; i < LL * 2 * NN; i += LL) {
        int l = i >> 5, j = i & 31;
        float v = g_xdbl[((size_t)(b * LL + l)) * NPROJ + RR + j];
        if (j < NN) sB[l][j] = v;
        else        sC[l][j - NN] = v;
    }
    __syncthreads();

    float Ar[NN];
#pragma unroll
    for (int n = 0; n < NN; n++) Ar[n] = -expf(A_logs[d * NN + n]);
    float Dd = Ds[d];

    float u[NN];
#pragma unroll
    for (int n = 0; n < NN; n++) u[n] = 0.f;

    for (int l = 0; l < LL; l++) {
        int m = b * LL + l;
        float dt = g_dts[(size_t)m * DD + d];
        float xv = g_xz [(size_t)m * DIN2 + d];
        float y = 0.f;
#pragma unroll
        for (int n = 0; n < NN; n++) {
            float a = __expf(dt * Ar[n]);
            u[n] = a * u[n] + dt * sB[l][n] * xv;
            y += u[n] * sC[l][n];
        }
        g_ssm[(size_t)m * DD + d] = y + Dd * xv;
    }

#pragma unroll
    for (int n = 0; n < NN; n++) u[n] = 0.f;
    for (int l = LL - 1; l >= 0; l--) {
        int m = b * LL + l;
        float dt = g_dts[(size_t)m * DD + d];
        float xv = g_xz [(size_t)m * DIN2 + d];
        float y = 0.f;
#pragma unroll
        for (int n = 0; n < NN; n++) {
            float a = __expf(dt * Ar[n]);
            u[n] = a * u[n] + dt * sB[l][n] * xv;
            y += u[n] * sC[l][n];
        }
        float tot = g_ssm[(size_t)m * DD + d] + y + Dd * xv;
        float z = g_xz[(size_t)m * DIN2 + DD + d];
        float sig = 1.f / (1.f + __expf(-z));
        g_ssm[(size_t)m * DD + d] = tot * (z * sig);
    }
}

// ---------------- launch ----------------
extern "C" void kernel_launch(void* const* d_in, const int* in_sizes, int n_in,
                              void* d_out, int out_size)
{
    const float* feat_map = (const float*)d_in[0];
    const float* ln_w     = (const float*)d_in[1];
    const float* ln_b     = (const float*)d_in[2];
    const float* in_w     = (const float*)d_in[3];
    const float* in_b     = (const float*)d_in[4];
    const float* x_proj_w = (const float*)d_in[5];
    const float* dt_w     = (const float*)d_in[6];
    const float* A_logs   = (const float*)d_in[7];
    const float* Ds       = (const float*)d_in[8];
    const float* out_w    = (const float*)d_in[9];
    const float* out_b    = (const float*)d_in[10];
    const float* mo_w     = (const float*)d_in[11];
    const float* mo_b     = (const float*)d_in[12];
    const float* bn_w     = (const float*)d_in[13];
    const float* bn_b     = (const float*)d_in[14];
    const float* bn_rm    = (const float*)d_in[15];
    const float* bn_rv    = (const float*)d_in[16];
    float* out = (float*)d_out;

    float *fm32, *out132, *xz, *ssm;
    int8_t *fmq, *out1q, *ssmq, *inwq, *outwq, *mowq;
    float *fms, *out1s, *ssms, *inws, *outws, *mows;
    cudaGetSymbolAddress((void**)&fm32,   g_fm32);
    cudaGetSymbolAddress((void**)&out132, g_out132);
    cudaGetSymbolAddress((void**)&xz,     g_xz);
    cudaGetSymbolAddress((void**)&ssm,    g_ssm);
    cudaGetSymbolAddress((void**)&fmq,    g_fmq);
    cudaGetSymbolAddress((void**)&out1q,  g_out1q);
    cudaGetSymbolAddress((void**)&ssmq,   g_ssmq);
    cudaGetSymbolAddress((void**)&inwq,   g_inwq);
    cudaGetSymbolAddress((void**)&outwq,  g_outwq);
    cudaGetSymbolAddress((void**)&mowq,   g_mowq);
    cudaGetSymbolAddress((void**)&fms,    g_fms);
    cudaGetSymbolAddress((void**)&out1s,  g_out1s);
    cudaGetSymbolAddress((void**)&ssms,   g_ssms);
    cudaGetSymbolAddress((void**)&inws,   g_inws);
    cudaGetSymbolAddress((void**)&outws,  g_outws);
    cudaGetSymbolAddress((void**)&mows,   g_mows);

    const int SMEM = 4 * 2 * 128 * 128;   // 131072
    cudaFuncSetAttribute(gemm_s8<0>, cudaFuncAttributeMaxDynamicSharedMemorySize, SMEM);
    cudaFuncSetAttribute(gemm_s8<1>, cudaFuncAttributeMaxDynamicSharedMemorySize, SMEM);
    cudaFuncSetAttribute(gemm_s8<2>, cudaFuncAttributeMaxDynamicSharedMemorySize, SMEM);

    // 1. transpose + LN -> fm fp32; quantize fm + weights
    ln_kernel<<<MM, 256>>>(feat_map, ln_w, ln_b);
    quant_kernel<0><<<(MM + 7) / 8, 256>>>(fm32, fmq, fms, CC, CC, MM);
    quant_kernel<1><<<(DIN2 + 7) / 8, 256>>>(in_w,  inwq,  inws,  CC, CC, DIN2);
    quant_kernel<1><<<(CC + 7) / 8, 256>>>(out_w, outwq, outws, DD, DDP, CC);
    quant_kernel<1><<<(CC + 7) / 8, 256>>>(mo_w,  mowq,  mows,  CC, CC, CC);

    // 2. in-projection -> xz fp32
    gemm_s8<0><<<dim3(DIN2 / 128, MM / 128), 256, SMEM>>>(
        fmq, inwq, fms, inws, KQ_C, KQ_C / 3 / 128, DIN2,
        in_b, nullptr, xz, nullptr, nullptr, nullptr, nullptr);

    // 3. x-proj + dt
    xproj_kernel<<<(MM * NPROJ + 255) / 256, 256>>>(x_proj_w);
    dt_kernel<<<(MM * DD) / 256, 256>>>(dt_w);

    // 4. scan + gate -> ssm fp32; quantize
    scan_kernel<<<BSZ, DD>>>(A_logs, Ds);
    quant_kernel<0><<<(MM + 7) / 8, 256>>>(ssm, ssmq, ssms, DD, DDP, MM);

    // 5. out-projection + fm residual -> out1 fp32; quantize
    gemm_s8<1><<<dim3(CC / 128, MM / 128), 256, SMEM>>>(
        ssmq, outwq, ssms, outws, KQ_D, KQ_D / 3 / 128, CC,
        out_b, fm32, out132, nullptr, nullptr, nullptr, nullptr);
    quant_kernel<0><<<(MM + 7) / 8, 256>>>(out132, out1q, out1s, CC, CC, MM);

    // 6. mixer GEMM + BN + ReLU + NCHW
    gemm_s8<2><<<dim3(CC / 128, MM / 128), 256, SMEM>>>(
        out1q, mowq, out1s, mows, KQ_C, KQ_C / 3 / 128, CC,
        mo_b, nullptr, out, bn_rm, bn_rv, bn_w, bn_b);
}

// round 12
// speedup vs baseline: 1.1213x; 1.1213x over previous
#include <cuda_runtime.h>
#include <cuda_bf16.h>
#include <cstdint>

// ---------------- problem constants ----------------
#define BSZ   64
#define CC    2048
#define LL    192
#define DIN2  384
#define DD    192
#define NN    16
#define RR    6
#define MM    (BSZ*LL)     // 12288
#define NPROJ 38
#define KIN   (3*CC)       // 6144
#define KOUT  (3*DD)       // 576

// ---------------- scratch ----------------
__device__ float g_xz  [(size_t)MM*DIN2];
__device__ float g_xdbl[(size_t)MM*NPROJ];
__device__ float g_dts [(size_t)MM*DD];
__device__ float g_ssm [(size_t)MM*DD];
__device__ __align__(128) __nv_bfloat16 g_fm_e  [(size_t)MM*KIN];
__device__ __align__(128) __nv_bfloat16 g_out1_e[(size_t)MM*KIN];
__device__ __align__(128) __nv_bfloat16 g_ssm_e [(size_t)MM*KOUT];
__device__ __align__(128) __nv_bfloat16 g_inw_e [(size_t)DIN2*KIN];
__device__ __align__(128) __nv_bfloat16 g_outw_e[(size_t)CC*KOUT];
__device__ __align__(128) __nv_bfloat16 g_mow_e [(size_t)CC*KIN];

// ---------------- helpers ----------------
__device__ __forceinline__ uint32_t smem_to_u32(const void* p) {
    uint32_t a;
    asm("{ .reg .u64 t; cvta.to.shared.u64 t, %1; cvt.u32.u64 %0, t; }" : "=r"(a) : "l"(p));
    return a;
}
#define SMEM_SWIZZLE_128B(off) ((off) ^ (((off) >> 3) & 0x70))

#define CP_ASYNC16(smem_u32, gptr) \
    asm volatile("cp.async.cg.shared.global [%0], [%1], 16;" \
                 :: "r"(smem_u32), "l"(__cvta_generic_to_global((const void*)(gptr))) : "memory")
#define CP_ASYNC_COMMIT() asm volatile("cp.async.commit_group;" ::: "memory")
#define CP_ASYNC_WAIT_2() asm volatile("cp.async.wait_group 2;" ::: "memory")

#define LDSM_X4(r0, r1, r2, r3, addr) \
    asm volatile("ldmatrix.sync.aligned.m8n8.x4.shared.b16 {%0,%1,%2,%3}, [%4];" \
                 : "=r"(r0), "=r"(r1), "=r"(r2), "=r"(r3) : "r"(addr))

#define MMA_BF16(d, a, b0, b1) \
    asm volatile("mma.sync.aligned.m16n8k16.row.col.f32.bf16.bf16.f32 " \
                 "{%0,%1,%2,%3}, {%4,%5,%6,%7}, {%8,%9}, {%0,%1,%2,%3};" \
                 : "+f"((d)[0]), "+f"((d)[1]), "+f"((d)[2]), "+f"((d)[3]) \
                 : "r"((a)[0]), "r"((a)[1]), "r"((a)[2]), "r"((a)[3]), \
                   "r"(b0), "r"(b1))

// ---------------- split-bf16 helpers ----------------
// Activations (A operand):  [hi, lo, hi]
// Weights     (B operand):  [hi, hi, lo]
// K'-dot = Ah*Bh + Al*Bh + Ah*Bl  (drops only Al*Bl ~ 2^-18 relative)
__device__ __forceinline__ void split3a(float v, __nv_bfloat16* row, int K, int c) {
    __nv_bfloat16 h = __float2bfloat16(v);
    float lo = v - __bfloat162float(h);
    row[c] = h;
    row[K + c] = __float2bfloat16(lo);
    row[2 * K + c] = h;
}
__device__ __forceinline__ void split3w(float v, __nv_bfloat16* row, int K, int c) {
    __nv_bfloat16 h = __float2bfloat16(v);
    float lo = v - __bfloat162float(h);
    row[c] = h;
    row[K + c] = h;
    row[2 * K + c] = __float2bfloat16(lo);
}

// ---------------- 1. transpose + LayerNorm -> split-bf16 fm ----------------
__global__ void ln_kernel(const float* __restrict__ x,
                          const float* __restrict__ w,
                          const float* __restrict__ b)
{
    int m  = blockIdx.x;
    int bb = m / LL, l = m % LL;
    const float* src = x + (size_t)bb * CC * LL + l;

    float v[8];
    float s = 0.f, s2 = 0.f;
#pragma unroll
    for (int k = 0; k < 8; k++) {
        int c = threadIdx.x + k * 256;
        float t = src[(size_t)c * LL];
        v[k] = t; s += t; s2 += t * t;
    }
    __shared__ float sred[64];
#pragma unroll
    for (int o = 16; o > 0; o >>= 1) {
        s  += __shfl_down_sync(0xffffffffu, s,  o);
        s2 += __shfl_down_sync(0xffffffffu, s2, o);
    }
    int wid = threadIdx.x >> 5, lane = threadIdx.x & 31;
    if (lane == 0) { sred[wid] = s; sred[32 + wid] = s2; }
    __syncthreads();
    if (threadIdx.x == 0) {
        float a = 0.f, a2 = 0.f;
#pragma unroll
        for (int i = 0; i < 8; i++) { a += sred[i]; a2 += sred[32 + i]; }
        sred[0] = a; sred[32] = a2;
    }
    __syncthreads();
    s = sred[0]; s2 = sred[32];

    float mu   = s * (1.f / CC);
    float var  = s2 * (1.f / CC) - mu * mu;
    float rstd = rsqrtf(var + 1e-5f);

    __nv_bfloat16* dst = g_fm_e + (size_t)m * KIN;
#pragma unroll
    for (int k = 0; k < 8; k++) {
        int c = threadIdx.x + k * 256;
        float fv = (v[k] - mu) * rstd * w[c] + b[c];
        split3a(fv, dst, CC, c);
    }
}

// ---------------- weight split-convert ----------------
__global__ void wconv_kernel(const float* __restrict__ w, __nv_bfloat16* __restrict__ o,
                             int K, int total)
{
    int idx = blockIdx.x * blockDim.x + threadIdx.x;
    if (idx >= total) return;
    int r = idx / K, c = idx % K;
    split3w(w[idx], o + (size_t)r * 3 * K, K, c);
}

// ---------------- mma.sync bf16 GEMM: C = A(M x K') * B(N x K')^T ----------------
// 128 x BN block, BK=64, 4-stage cp.async (distance 2), single sync per iter,
// warp grid TM x TN (threads = TM*TN*32), warp tile (128/TM) x (BN/TN),
// ldmatrix fragments (validated mapping).
template <int BN, int TM, int TN, int EPI>
__global__ void __launch_bounds__(TM * TN * 32) gemm_mma(
    const __nv_bfloat16* __restrict__ A, const __nv_bfloat16* __restrict__ B,
    int K, int Nout,
    const float* __restrict__ bias,
    const __nv_bfloat16* __restrict__ resid,
    float* __restrict__ Cf, __nv_bfloat16* __restrict__ Cb,
    const float* __restrict__ bn_rm, const float* __restrict__ bn_rv,
    const float* __restrict__ bn_w,  const float* __restrict__ bn_b)
{
    constexpr int S      = 4;                 // pipeline stages
    constexpr int THR    = TM * TN * 32;
    constexpr int ABYTES = 128 * 128;         // 128 rows x 64 bf16
    constexpr int BBYTES = BN * 128;
    constexpr int STAGE  = ABYTES + BBYTES;
    constexpr int MI     = 128 / TM / 16;     // 16-row A groups per warp
    constexpr int NT     = BN / TN / 16;      // 16-row B ldmatrix groups per warp
    constexpr int NI     = BN / TN / 8;       // 8-col mma subtiles per warp
    constexpr int AITER  = 1024 / THR;        // A 16B-chunks per thread
    constexpr int BITER  = BN * 8 / THR;      // B 16B-chunks per thread

    extern __shared__ char smem[];
    uint32_t sb = smem_to_u32(smem);

    int tid = threadIdx.x, wid = tid >> 5, lane = tid & 31;
    int m0 = blockIdx.y * 128, n0 = blockIdx.x * BN;
    int wm0 = (wid % TM) * (128 / TM);       // warp m offset
    int wn0 = (wid / TM) * (BN / TN);        // warp n offset

    int lrow8 = lane & 7;
    int g     = lane >> 3;                   // ldmatrix 8x8 matrix index
    int mg    = (g & 1) * 8;                 // row offset within 16
    int kg    = (g >> 1) * 8;                // k offset within 16

    float acc[MI][NI][4];
#pragma unroll
    for (int i = 0; i < MI; i++)
#pragma unroll
        for (int j = 0; j < NI; j++)
#pragma unroll
            for (int q = 0; q < 4; q++) acc[i][j][q] = 0.f;

    const int T = K / 64;

    int lrow = tid >> 3;                     // 0..THR/8-1
    int lcol = tid & 7;                      // 16B chunk col
    auto load = [&](int j) {
        uint32_t abase = sb + (j % S) * STAGE;
        uint32_t bbase = abase + ABYTES;
        int k0 = j * 64;
#pragma unroll
        for (int c = 0; c < AITER; c++) {
            int row = lrow + c * (THR / 8);
            uint32_t soff = SMEM_SWIZZLE_128B((uint32_t)(row * 128 + lcol * 16));
            CP_ASYNC16(abase + soff, A + (size_t)(m0 + row) * K + k0 + lcol * 8);
        }
#pragma unroll
        for (int c = 0; c < BITER; c++) {
            int row = lrow + c * (THR / 8);
            uint32_t soff = SMEM_SWIZZLE_128B((uint32_t)(row * 128 + lcol * 16));
            CP_ASYNC16(bbase + soff, B + (size_t)(n0 + row) * K + k0 + lcol * 8);
        }
    };

    load(0); CP_ASYNC_COMMIT();
    load(1); CP_ASYNC_COMMIT();

    for (int i = 0; i < T; i++) {
        // prefetch first, then wait for stage i: pending {i, i+1, i+2} -> wait<=2
        if (i + 2 < T) load(i + 2);
        CP_ASYNC_COMMIT();
        CP_ASYNC_WAIT_2();
        __syncthreads();
        // S=4, distance 2, single barrier: writes hit stage (i+2)%4, reads i%4.

        uint32_t abase = sb + (i % S) * STAGE;
        uint32_t bbase = abase + ABYTES;

#pragma unroll
        for (int kk = 0; kk < 4; kk++) {
            int coff = (kk * 16 + kg) * 2;
            uint32_t a[MI][4], b[NT][4];
#pragma unroll
            for (int mi = 0; mi < MI; mi++) {
                int row = wm0 + mi * 16 + lrow8 + mg;
                uint32_t ad = abase + SMEM_SWIZZLE_128B((uint32_t)(row * 128 + coff));
                LDSM_X4(a[mi][0], a[mi][1], a[mi][2], a[mi][3], ad);
            }
#pragma unroll
            for (int nt = 0; nt < NT; nt++) {
                int row = wn0 + nt * 16 + lrow8 + mg;
                uint32_t bd = bbase + SMEM_SWIZZLE_128B((uint32_t)(row * 128 + coff));
                LDSM_X4(b[nt][0], b[nt][1], b[nt][2], b[nt][3], bd);
            }
#pragma unroll
            for (int mi = 0; mi < MI; mi++) {
#pragma unroll
                for (int nt = 0; nt < NT; nt++) {
                    MMA_BF16(acc[mi][nt * 2 + 0], a[mi], b[nt][0], b[nt][2]);
                    MMA_BF16(acc[mi][nt * 2 + 1], a[mi], b[nt][1], b[nt][3]);
                }
            }
        }
    }

    // ---------------- epilogue (registers only) ----------------
    int qrow = lane >> 2;
    int qcol = (lane & 3) * 2;
#pragma unroll
    for (int mi = 0; mi < MI; mi++) {
#pragma unroll
        for (int ni = 0; ni < NI; ni++) {
#pragma unroll
            for (int h = 0; h < 2; h++) {
#pragma unroll
                for (int q = 0; q < 2; q++) {
                    int m = m0 + wm0 + mi * 16 + qrow + h * 8;
                    int n = n0 + wn0 + ni * 8 + qcol + q;
                    float v = acc[mi][ni][h * 2 + q] + bias[n];
                    if (EPI == 0) {
                        Cf[(size_t)m * Nout + n] = v;
                    } else if (EPI == 1) {
                        v += __bfloat162float(resid[(size_t)m * KIN + n])
                           + __bfloat162float(resid[(size_t)m * KIN + CC + n]);
                        split3a(v, Cb + (size_t)m * KIN, CC, n);
                    } else {
                        float rs = rsqrtf(bn_rv[n] + 1e-5f);
                        v = (v - bn_rm[n]) * rs * bn_w[n] + bn_b[n];
                        v = fmaxf(v, 0.f);
                        int bb = m / LL, l = m - bb * LL;
                        Cf[((size_t)bb * CC + n) * LL + l] = v;
                    }
                }
            }
        }
    }
}

// ---------------- x_proj ----------------
__global__ void xproj_kernel(const float* __restrict__ xpw)
{
    int idx = blockIdx.x * blockDim.x + threadIdx.x;
    if (idx >= MM * NPROJ) return;
    int m = idx / NPROJ, j = idx % NPROJ;
    const float* xr = g_xz + (size_t)m * DIN2;
    const float* wr = xpw + j * DD;
    float acc = 0.f;
#pragma unroll 8
    for (int k = 0; k < DD; k++) acc += xr[k] * wr[k];
    g_xdbl[idx] = acc;
}

// ---------------- dt softplus ----------------
__global__ void dt_kernel(const float* __restrict__ dtw)
{
    int idx = blockIdx.x * blockDim.x + threadIdx.x;
    if (idx >= MM * DD) return;
    int m = idx / DD, d = idx % DD;
    const float* xd = g_xdbl + (size_t)m * NPROJ;
    float acc = 0.f;
#pragma unroll
    for (int r = 0; r < RR; r++) acc += xd[r] * dtw[d * RR + r];
    float sp = (acc > 20.f) ? acc : log1pf(__expf(acc));
    g_dts[idx] = sp;
}

// ---------------- bidirectional scan + SiLU gate -> split-bf16 ssm ----------------
__global__ void scan_kernel(const float* __restrict__ A_logs,
                            const float* __restrict__ Ds)
{
    __shared__ float sB[LL][NN];
    __shared__ float sC[LL][NN];
    int b = blockIdx.x, d = threadIdx.x;

    for (int i = d; i < LL * 2 * NN; i += LL) {
        int l = i >> 5, j = i & 31;
        float v = g_xdbl[((size_t)(b * LL + l)) * NPROJ + RR + j];
        if (j < NN) sB[l][j] = v;
        else        sC[l][j - NN] = v;
    }
    __syncthreads();

    float Ar[NN];
#pragma unroll
    for (int n = 0; n < NN; n++) Ar[n] = -expf(A_logs[d * NN + n]);
    float Dd = Ds[d];

    float u[NN];
#pragma unroll
    for (int n = 0; n < NN; n++) u[n] = 0.f;

    for (int l = 0; l < LL; l++) {
        int m = b * LL + l;
        float dt = g_dts[(size_t)m * DD + d];
        float xv = g_xz [(size_t)m * DIN2 + d];
        float y = 0.f;
#pragma unroll
        for (int n = 0; n < NN; n++) {
            float a = __expf(dt * Ar[n]);
            u[n] = a * u[n] + dt * sB[l][n] * xv;
            y += u[n] * sC[l][n];
        }
        g_ssm[(size_t)m * DD + d] = y + Dd * xv;
    }

#pragma unroll
    for (int n = 0; n < NN; n++) u[n] = 0.f;
    for (int l = LL - 1; l >= 0; l--) {
        int m = b * LL + l;
        float dt = g_dts[(size_t)m * DD + d];
        float xv = g_xz [(size_t)m * DIN2 + d];
        float y = 0.f;
#pragma unroll
        for (int n = 0; n < NN; n++) {
            float a = __expf(dt * Ar[n]);
            u[n] = a * u[n] + dt * sB[l][n] * xv;
            y += u[n] * sC[l][n];
        }
        float tot = g_ssm[(size_t)m * DD + d] + y + Dd * xv;
        float z = g_xz[(size_t)m * DIN2 + DD + d];
        float sig = 1.f / (1.f + __expf(-z));
        split3a(tot * (z * sig), g_ssm_e + (size_t)m * KOUT, DD, d);
    }
}

// ---------------- launch ----------------
extern "C" void kernel_launch(void* const* d_in, const int* in_sizes, int n_in,
                              void* d_out, int out_size)
{
    const float* feat_map = (const float*)d_in[0];
    const float* ln_w     = (const float*)d_in[1];
    const float* ln_b     = (const float*)d_in[2];
    const float* in_w     = (const float*)d_in[3];
    const float* in_b     = (const float*)d_in[4];
    const float* x_proj_w = (const float*)d_in[5];
    const float* dt_w     = (const float*)d_in[6];
    const float* A_logs   = (const float*)d_in[7];
    const float* Ds       = (const float*)d_in[8];
    const float* out_w    = (const float*)d_in[9];
    const float* out_b    = (const float*)d_in[10];
    const float* mo_w     = (const float*)d_in[11];
    const float* mo_b     = (const float*)d_in[12];
    const float* bn_w     = (const float*)d_in[13];
    const float* bn_b     = (const float*)d_in[14];
    const float* bn_rm    = (const float*)d_in[15];
    const float* bn_rv    = (const float*)d_in[16];
    float* out = (float*)d_out;

    __nv_bfloat16 *fm_e, *out1_e, *ssm_e, *inw_e, *outw_e, *mow_e;
    float *xz;
    cudaGetSymbolAddress((void**)&fm_e,   g_fm_e);
    cudaGetSymbolAddress((void**)&out1_e, g_out1_e);
    cudaGetSymbolAddress((void**)&ssm_e,  g_ssm_e);
    cudaGetSymbolAddress((void**)&inw_e,  g_inw_e);
    cudaGetSymbolAddress((void**)&outw_e, g_outw_e);
    cudaGetSymbolAddress((void**)&mow_e,  g_mow_e);
    cudaGetSymbolAddress((void**)&xz,     g_xz);

    const int SMEM128 = 4 * (128 + 128) * 128;   // 131072
    const int SMEM256 = 4 * (128 + 256) * 128;   // 196608
    cudaFuncSetAttribute((gemm_mma<128, 2, 4, 0>), cudaFuncAttributeMaxDynamicSharedMemorySize, SMEM128);
    cudaFuncSetAttribute((gemm_mma<256, 4, 4, 1>), cudaFuncAttributeMaxDynamicSharedMemorySize, SMEM256);
    cudaFuncSetAttribute((gemm_mma<256, 4, 4, 2>), cudaFuncAttributeMaxDynamicSharedMemorySize, SMEM256);

    // 1. transpose + LN -> fm split-bf16 (activation layout)
    ln_kernel<<<MM, 256>>>(feat_map, ln_w, ln_b);

    // weight conversions (weight layout [h, h, lo])
    wconv_kernel<<<(DIN2 * CC + 255) / 256, 256>>>(in_w,  inw_e,  CC, DIN2 * CC);
    wconv_kernel<<<(CC * DD   + 255) / 256, 256>>>(out_w, outw_e, DD, CC * DD);
    wconv_kernel<<<(CC * CC   + 255) / 256, 256>>>(mo_w,  mow_e,  CC, CC * CC);

    // 2. in-projection: xz = fm @ in_w^T + in_b  (fp32 out) — 256 thr, 64x32 warps
    gemm_mma<128, 2, 4, 0><<<dim3(DIN2 / 128, MM / 128), 256, SMEM128>>>(
        fm_e, inw_e, KIN, DIN2, in_b, nullptr, xz, nullptr,
        nullptr, nullptr, nullptr, nullptr);

    // 3. x-proj + dt
    xproj_kernel<<<(MM * NPROJ + 255) / 256, 256>>>(x_proj_w);
    dt_kernel<<<(MM * DD) / 256, 256>>>(dt_w);

    // 4. scan + gate -> ssm split-bf16 (activation layout)
    scan_kernel<<<BSZ, DD>>>(A_logs, Ds);

    // 5. out-projection + fm residual -> out1 split-bf16 — 512 thr, 32x64 warps
    gemm_mma<256, 4, 4, 1><<<dim3(CC / 256, MM / 128), 512, SMEM256>>>(
        ssm_e, outw_e, KOUT, CC, out_b, fm_e, nullptr, out1_e,
        nullptr, nullptr, nullptr, nullptr);

    // 6. mixer GEMM + BN + ReLU + NCHW write — 512 thr, 32x64 warps
    gemm_mma<256, 4, 4, 2><<<dim3(CC / 256, MM / 128), 512, SMEM256>>>(
        out1_e, mow_e, KIN, CC, mo_b, nullptr, out, nullptr,
        bn_rm, bn_rv, bn_w, bn_b);
}

// round 13
// speedup vs baseline: 1.8034x; 1.6083x over previous
#include <cuda_runtime.h>
#include <cuda_bf16.h>
#include <cstdint>

// ---------------- problem constants ----------------
#define BSZ   64
#define CC    2048
#define LL    192
#define DIN2  384
#define DD    192
#define NN    16
#define RR    6
#define MM    (BSZ*LL)     // 12288
#define NPROJ 38
#define KIN   (3*CC)       // 6144
#define KOUT  (3*DD)       // 576

// ---------------- scratch ----------------
__device__ float g_xz  [(size_t)MM*DIN2];
__device__ float g_xdbl[(size_t)MM*NPROJ];
__device__ float g_dts [(size_t)MM*DD];
__device__ float g_ssm [(size_t)MM*DD];
__device__ __align__(128) __nv_bfloat16 g_fm_e  [(size_t)MM*KIN];
__device__ __align__(128) __nv_bfloat16 g_out1_e[(size_t)MM*KIN];
__device__ __align__(128) __nv_bfloat16 g_ssm_e [(size_t)MM*KOUT];
__device__ __align__(128) __nv_bfloat16 g_inw_e [(size_t)DIN2*KIN];
__device__ __align__(128) __nv_bfloat16 g_outw_e[(size_t)CC*KOUT];
__device__ __align__(128) __nv_bfloat16 g_mow_e [(size_t)CC*KIN];

// ---------------- helpers ----------------
__device__ __forceinline__ uint32_t smem_to_u32(const void* p) {
    uint32_t a;
    asm("{ .reg .u64 t; cvta.to.shared.u64 t, %1; cvt.u32.u64 %0, t; }" : "=r"(a) : "l"(p));
    return a;
}
#define SMEM_SWIZZLE_128B(off) ((off) ^ (((off) >> 3) & 0x70))

#define CP_ASYNC16(smem_u32, gptr) \
    asm volatile("cp.async.cg.shared.global [%0], [%1], 16;" \
                 :: "r"(smem_u32), "l"(__cvta_generic_to_global((const void*)(gptr))) : "memory")
#define CP_ASYNC_COMMIT() asm volatile("cp.async.commit_group;" ::: "memory")
#define CP_ASYNC_WAIT_2() asm volatile("cp.async.wait_group 2;" ::: "memory")

#define LDSM_X4(r0, r1, r2, r3, addr) \
    asm volatile("ldmatrix.sync.aligned.m8n8.x4.shared.b16 {%0,%1,%2,%3}, [%4];" \
                 : "=r"(r0), "=r"(r1), "=r"(r2), "=r"(r3) : "r"(addr))

#define MMA_BF16(d, a, b0, b1) \
    asm volatile("mma.sync.aligned.m16n8k16.row.col.f32.bf16.bf16.f32 " \
                 "{%0,%1,%2,%3}, {%4,%5,%6,%7}, {%8,%9}, {%0,%1,%2,%3};" \
                 : "+f"((d)[0]), "+f"((d)[1]), "+f"((d)[2]), "+f"((d)[3]) \
                 : "r"((a)[0]), "r"((a)[1]), "r"((a)[2]), "r"((a)[3]), \
                   "r"(b0), "r"(b1))

// ---------------- split-bf16 helpers ----------------
// Activations (A operand):  [hi, lo, hi]
// Weights     (B operand):  [hi, hi, lo]
// K'-dot = Ah*Bh + Al*Bh + Ah*Bl  (drops only Al*Bl ~ 2^-18 relative)
__device__ __forceinline__ void split3a(float v, __nv_bfloat16* row, int K, int c) {
    __nv_bfloat16 h = __float2bfloat16(v);
    float lo = v - __bfloat162float(h);
    row[c] = h;
    row[K + c] = __float2bfloat16(lo);
    row[2 * K + c] = h;
}
__device__ __forceinline__ void split3w(float v, __nv_bfloat16* row, int K, int c) {
    __nv_bfloat16 h = __float2bfloat16(v);
    float lo = v - __bfloat162float(h);
    row[c] = h;
    row[K + c] = h;
    row[2 * K + c] = __float2bfloat16(lo);
}

// ---------------- 1. transpose + LayerNorm -> split-bf16 fm ----------------
__global__ void ln_kernel(const float* __restrict__ x,
                          const float* __restrict__ w,
                          const float* __restrict__ b)
{
    int m  = blockIdx.x;
    int bb = m / LL, l = m % LL;
    const float* src = x + (size_t)bb * CC * LL + l;

    float v[8];
    float s = 0.f, s2 = 0.f;
#pragma unroll
    for (int k = 0; k < 8; k++) {
        int c = threadIdx.x + k * 256;
        float t = src[(size_t)c * LL];
        v[k] = t; s += t; s2 += t * t;
    }
    __shared__ float sred[64];
#pragma unroll
    for (int o = 16; o > 0; o >>= 1) {
        s  += __shfl_down_sync(0xffffffffu, s,  o);
        s2 += __shfl_down_sync(0xffffffffu, s2, o);
    }
    int wid = threadIdx.x >> 5, lane = threadIdx.x & 31;
    if (lane == 0) { sred[wid] = s; sred[32 + wid] = s2; }
    __syncthreads();
    if (threadIdx.x == 0) {
        float a = 0.f, a2 = 0.f;
#pragma unroll
        for (int i = 0; i < 8; i++) { a += sred[i]; a2 += sred[32 + i]; }
        sred[0] = a; sred[32] = a2;
    }
    __syncthreads();
    s = sred[0]; s2 = sred[32];

    float mu   = s * (1.f / CC);
    float var  = s2 * (1.f / CC) - mu * mu;
    float rstd = rsqrtf(var + 1e-5f);

    __nv_bfloat16* dst = g_fm_e + (size_t)m * KIN;
#pragma unroll
    for (int k = 0; k < 8; k++) {
        int c = threadIdx.x + k * 256;
        float fv = (v[k] - mu) * rstd * w[c] + b[c];
        split3a(fv, dst, CC, c);
    }
}

// ---------------- weight split-convert ----------------
__global__ void wconv_kernel(const float* __restrict__ w, __nv_bfloat16* __restrict__ o,
                             int K, int total)
{
    int idx = blockIdx.x * blockDim.x + threadIdx.x;
    if (idx >= total) return;
    int r = idx / K, c = idx % K;
    split3w(w[idx], o + (size_t)r * 3 * K, K, c);
}

// ---------------- mma.sync bf16 GEMM: C = A(M x K') * B(N x K')^T ----------------
// BM x BN block, BK=64, 4-stage cp.async (distance 2), single sync per iter,
// 8 warps fixed (2m x 4n), warp tile (BM/2) x (BN/4), ldmatrix fragments.
// BM in {96,128}: BM=96 gives grid sizes near multiples of 148 (wave-tail fix).
template <int BM, int BN, int EPI>
__global__ void __launch_bounds__(256) gemm_mma(
    const __nv_bfloat16* __restrict__ A, const __nv_bfloat16* __restrict__ B,
    int K, int Nout,
    const float* __restrict__ bias,
    const __nv_bfloat16* __restrict__ resid,
    float* __restrict__ Cf, __nv_bfloat16* __restrict__ Cb,
    const float* __restrict__ bn_rm, const float* __restrict__ bn_rv,
    const float* __restrict__ bn_w,  const float* __restrict__ bn_b)
{
    constexpr int S      = 4;                 // pipeline stages
    constexpr int ABYTES = BM * 128;          // BM rows x 64 bf16
    constexpr int BBYTES = BN * 128;
    constexpr int STAGE  = ABYTES + BBYTES;
    constexpr int MI     = BM / 32;           // 16-row A groups per warp (TM=2)
    constexpr int NT     = BN / 64;           // 16-row B ldmatrix groups per warp (TN=4)
    constexpr int NI     = BN / 32;           // 8-col mma subtiles per warp
    constexpr int AITER  = BM / 32;           // A 16B-chunks per thread (256 thr)
    constexpr int BITER  = BN / 32;           // B 16B-chunks per thread

    extern __shared__ char smem[];
    uint32_t sb = smem_to_u32(smem);

    int tid = threadIdx.x, wid = tid >> 5, lane = tid & 31;
    int m0 = blockIdx.y * BM, n0 = blockIdx.x * BN;
    int wm0 = (wid & 1) * (BM / 2);          // warp m offset
    int wn0 = (wid >> 1) * (BN / 4);         // warp n offset

    int lrow8 = lane & 7;
    int g     = lane >> 3;                   // ldmatrix 8x8 matrix index
    int mg    = (g & 1) * 8;                 // row offset within 16
    int kg    = (g >> 1) * 8;                // k offset within 16

    float acc[MI][NI][4];
#pragma unroll
    for (int i = 0; i < MI; i++)
#pragma unroll
        for (int j = 0; j < NI; j++)
#pragma unroll
            for (int q = 0; q < 4; q++) acc[i][j][q] = 0.f;

    const int T = K / 64;

    int lrow = tid >> 3;                     // 0..31
    int lcol = tid & 7;                      // 16B chunk col
    auto load = [&](int j) {
        uint32_t abase = sb + (j % S) * STAGE;
        uint32_t bbase = abase + ABYTES;
        int k0 = j * 64;
#pragma unroll
        for (int c = 0; c < AITER; c++) {
            int row = lrow + c * 32;
            uint32_t soff = SMEM_SWIZZLE_128B((uint32_t)(row * 128 + lcol * 16));
            CP_ASYNC16(abase + soff, A + (size_t)(m0 + row) * K + k0 + lcol * 8);
        }
#pragma unroll
        for (int c = 0; c < BITER; c++) {
            int row = lrow + c * 32;
            uint32_t soff = SMEM_SWIZZLE_128B((uint32_t)(row * 128 + lcol * 16));
            CP_ASYNC16(bbase + soff, B + (size_t)(n0 + row) * K + k0 + lcol * 8);
        }
    };

    load(0); CP_ASYNC_COMMIT();
    load(1); CP_ASYNC_COMMIT();

    for (int i = 0; i < T; i++) {
        // prefetch first, then wait for stage i: pending {i, i+1, i+2} -> wait<=2
        if (i + 2 < T) load(i + 2);
        CP_ASYNC_COMMIT();
        CP_ASYNC_WAIT_2();
        __syncthreads();
        // S=4, distance 2, single barrier: writes hit stage (i+2)%4, reads i%4.

        uint32_t abase = sb + (i % S) * STAGE;
        uint32_t bbase = abase + ABYTES;

#pragma unroll
        for (int kk = 0; kk < 4; kk++) {
            int coff = (kk * 16 + kg) * 2;
            uint32_t a[MI][4], b[NT][4];
#pragma unroll
            for (int mi = 0; mi < MI; mi++) {
                int row = wm0 + mi * 16 + lrow8 + mg;
                uint32_t ad = abase + SMEM_SWIZZLE_128B((uint32_t)(row * 128 + coff));
                LDSM_X4(a[mi][0], a[mi][1], a[mi][2], a[mi][3], ad);
            }
#pragma unroll
            for (int nt = 0; nt < NT; nt++) {
                int row = wn0 + nt * 16 + lrow8 + mg;
                uint32_t bd = bbase + SMEM_SWIZZLE_128B((uint32_t)(row * 128 + coff));
                LDSM_X4(b[nt][0], b[nt][1], b[nt][2], b[nt][3], bd);
            }
#pragma unroll
            for (int mi = 0; mi < MI; mi++) {
#pragma unroll
                for (int nt = 0; nt < NT; nt++) {
                    MMA_BF16(acc[mi][nt * 2 + 0], a[mi], b[nt][0], b[nt][2]);
                    MMA_BF16(acc[mi][nt * 2 + 1], a[mi], b[nt][1], b[nt][3]);
                }
            }
        }
    }

    // ---------------- epilogue (registers only) ----------------
    int qrow = lane >> 2;
    int qcol = (lane & 3) * 2;
#pragma unroll
    for (int mi = 0; mi < MI; mi++) {
#pragma unroll
        for (int ni = 0; ni < NI; ni++) {
#pragma unroll
            for (int h = 0; h < 2; h++) {
#pragma unroll
                for (int q = 0; q < 2; q++) {
                    int m = m0 + wm0 + mi * 16 + qrow + h * 8;
                    int n = n0 + wn0 + ni * 8 + qcol + q;
                    float v = acc[mi][ni][h * 2 + q] + bias[n];
                    if (EPI == 0) {
                        Cf[(size_t)m * Nout + n] = v;
                    } else if (EPI == 1) {
                        v += __bfloat162float(resid[(size_t)m * KIN + n])
                           + __bfloat162float(resid[(size_t)m * KIN + CC + n]);
                        split3a(v, Cb + (size_t)m * KIN, CC, n);
                    } else {
                        float rs = rsqrtf(bn_rv[n] + 1e-5f);
                        v = (v - bn_rm[n]) * rs * bn_w[n] + bn_b[n];
                        v = fmaxf(v, 0.f);
                        int bb = m / LL, l = m - bb * LL;
                        Cf[((size_t)bb * CC + n) * LL + l] = v;
                    }
                }
            }
        }
    }
}

// ---------------- x_proj ----------------
__global__ void xproj_kernel(const float* __restrict__ xpw)
{
    int idx = blockIdx.x * blockDim.x + threadIdx.x;
    if (idx >= MM * NPROJ) return;
    int m = idx / NPROJ, j = idx % NPROJ;
    const float* xr = g_xz + (size_t)m * DIN2;
    const float* wr = xpw + j * DD;
    float acc = 0.f;
#pragma unroll 8
    for (int k = 0; k < DD; k++) acc += xr[k] * wr[k];
    g_xdbl[idx] = acc;
}

// ---------------- dt softplus ----------------
__global__ void dt_kernel(const float* __restrict__ dtw)
{
    int idx = blockIdx.x * blockDim.x + threadIdx.x;
    if (idx >= MM * DD) return;
    int m = idx / DD, d = idx % DD;
    const float* xd = g_xdbl + (size_t)m * NPROJ;
    float acc = 0.f;
#pragma unroll
    for (int r = 0; r < RR; r++) acc += xd[r] * dtw[d * RR + r];
    float sp = (acc > 20.f) ? acc : log1pf(__expf(acc));
    g_dts[idx] = sp;
}

// ---------------- bidirectional scan + SiLU gate -> split-bf16 ssm ----------------
__global__ void scan_kernel(const float* __restrict__ A_logs,
                            const float* __restrict__ Ds)
{
    __shared__ float sB[LL][NN];
    __shared__ float sC[LL][NN];
    int b = blockIdx.x, d = threadIdx.x;

    for (int i = d; i < LL * 2 * NN; i += LL) {
        int l = i >> 5, j = i & 31;
        float v = g_xdbl[((size_t)(b * LL + l)) * NPROJ + RR + j];
        if (j < NN) sB[l][j] = v;
        else        sC[l][j - NN] = v;
    }
    __syncthreads();

    float Ar[NN];
#pragma unroll
    for (int n = 0; n < NN; n++) Ar[n] = -expf(A_logs[d * NN + n]);
    float Dd = Ds[d];

    float u[NN];
#pragma unroll
    for (int n = 0; n < NN; n++) u[n] = 0.f;

    for (int l = 0; l < LL; l++) {
        int m = b * LL + l;
        float dt = g_dts[(size_t)m * DD + d];
        float xv = g_xz [(size_t)m * DIN2 + d];
        float y = 0.f;
#pragma unroll
        for (int n = 0; n < NN; n++) {
            float a = __expf(dt * Ar[n]);
            u[n] = a * u[n] + dt * sB[l][n] * xv;
            y += u[n] * sC[l][n];
        }
        g_ssm[(size_t)m * DD + d] = y + Dd * xv;
    }

#pragma unroll
    for (int n = 0; n < NN; n++) u[n] = 0.f;
    for (int l = LL - 1; l >= 0; l--) {
        int m = b * LL + l;
        float dt = g_dts[(size_t)m * DD + d];
        float xv = g_xz [(size_t)m * DIN2 + d];
        float y = 0.f;
#pragma unroll
        for (int n = 0; n < NN; n++) {
            float a = __expf(dt * Ar[n]);
            u[n] = a * u[n] + dt * sB[l][n] * xv;
            y += u[n] * sC[l][n];
        }
        float tot = g_ssm[(size_t)m * DD + d] + y + Dd * xv;
        float z = g_xz[(size_t)m * DIN2 + DD + d];
        float sig = 1.f / (1.f + __expf(-z));
        split3a(tot * (z * sig), g_ssm_e + (size_t)m * KOUT, DD, d);
    }
}

// ---------------- launch ----------------
extern "C" void kernel_launch(void* const* d_in, const int* in_sizes, int n_in,
                              void* d_out, int out_size)
{
    const float* feat_map = (const float*)d_in[0];
    const float* ln_w     = (const float*)d_in[1];
    const float* ln_b     = (const float*)d_in[2];
    const float* in_w     = (const float*)d_in[3];
    const float* in_b     = (const float*)d_in[4];
    const float* x_proj_w = (const float*)d_in[5];
    const float* dt_w     = (const float*)d_in[6];
    const float* A_logs   = (const float*)d_in[7];
    const float* Ds       = (const float*)d_in[8];
    const float* out_w    = (const float*)d_in[9];
    const float* out_b    = (const float*)d_in[10];
    const float* mo_w     = (const float*)d_in[11];
    const float* mo_b     = (const float*)d_in[12];
    const float* bn_w     = (const float*)d_in[13];
    const float* bn_b     = (const float*)d_in[14];
    const float* bn_rm    = (const float*)d_in[15];
    const float* bn_rv    = (const float*)d_in[16];
    float* out = (float*)d_out;

    __nv_bfloat16 *fm_e, *out1_e, *ssm_e, *inw_e, *outw_e, *mow_e;
    float *xz;
    cudaGetSymbolAddress((void**)&fm_e,   g_fm_e);
    cudaGetSymbolAddress((void**)&out1_e, g_out1_e);
    cudaGetSymbolAddress((void**)&ssm_e,  g_ssm_e);
    cudaGetSymbolAddress((void**)&inw_e,  g_inw_e);
    cudaGetSymbolAddress((void**)&outw_e, g_outw_e);
    cudaGetSymbolAddress((void**)&mow_e,  g_mow_e);
    cudaGetSymbolAddress((void**)&xz,     g_xz);

    const int SMEM_IN  = 4 * (128 + 128) * 128;   // 131072  (BM=128, BN=128)
    const int SMEM_BIG = 4 * (96 + 256) * 128;    // 180224  (BM=96,  BN=256)
    cudaFuncSetAttribute((gemm_mma<128, 128, 0>), cudaFuncAttributeMaxDynamicSharedMemorySize, SMEM_IN);
    cudaFuncSetAttribute((gemm_mma<96, 256, 1>),  cudaFuncAttributeMaxDynamicSharedMemorySize, SMEM_BIG);
    cudaFuncSetAttribute((gemm_mma<96, 256, 2>),  cudaFuncAttributeMaxDynamicSharedMemorySize, SMEM_BIG);

    // 1. transpose + LN -> fm split-bf16 (activation layout)
    ln_kernel<<<MM, 256>>>(feat_map, ln_w, ln_b);

    // weight conversions (weight layout [h, h, lo])
    wconv_kernel<<<(DIN2 * CC + 255) / 256, 256>>>(in_w,  inw_e,  CC, DIN2 * CC);
    wconv_kernel<<<(CC * DD   + 255) / 256, 256>>>(out_w, outw_e, DD, CC * DD);
    wconv_kernel<<<(CC * CC   + 255) / 256, 256>>>(mo_w,  mow_e,  CC, CC * CC);

    // 2. in-projection: xz = fm @ in_w^T + in_b  (fp32 out) — proven 128x128 shape
    gemm_mma<128, 128, 0><<<dim3(DIN2 / 128, MM / 128), 256, SMEM_IN>>>(
        fm_e, inw_e, KIN, DIN2, in_b, nullptr, xz, nullptr,
        nullptr, nullptr, nullptr, nullptr);

    // 3. x-proj + dt
    xproj_kernel<<<(MM * NPROJ + 255) / 256, 256>>>(x_proj_w);
    dt_kernel<<<(MM * DD) / 256, 256>>>(dt_w);

    // 4. scan + gate -> ssm split-bf16 (activation layout)
    scan_kernel<<<BSZ, DD>>>(A_logs, Ds);

    // 5. out-projection + fm residual -> out1 split-bf16 — BM=96 (1024 CTAs, ~1% tail)
    gemm_mma<96, 256, 1><<<dim3(CC / 256, MM / 96), 256, SMEM_BIG>>>(
        ssm_e, outw_e, KOUT, CC, out_b, fm_e, nullptr, out1_e,
        nullptr, nullptr, nullptr, nullptr);

    // 6. mixer GEMM + BN + ReLU + NCHW write — BM=96 (1024 CTAs, ~1% tail)
    gemm_mma<96, 256, 2><<<dim3(CC / 256, MM / 96), 256, SMEM_BIG>>>(
        out1_e, mow_e, KIN, CC, mo_b, nullptr, out, nullptr,
        bn_rm, bn_rv, bn_w, bn_b);
}

// round 14
// speedup vs baseline: 2.0028x; 1.1106x over previous
#include <cuda_runtime.h>
#include <cuda_bf16.h>
#include <cstdint>

// ---------------- problem constants ----------------
#define BSZ   64
#define CC    2048
#define LL    192
#define DIN2  384
#define DD    192
#define NN    16
#define RR    6
#define MM    (BSZ*LL)     // 12288
#define NPROJ 38
#define KIN   (3*CC)       // 6144 (expanded K for weights, C-side)
#define KOUT  (3*DD)       // 576  (expanded K for weights, D-side)

// ---------------- scratch ----------------
__device__ float g_xz  [(size_t)MM*DIN2];
__device__ float g_xdbl[(size_t)MM*NPROJ];
__device__ float g_dts [(size_t)MM*DD];
__device__ float g_ssmf[(size_t)MM*DD];     // forward scan out
__device__ float g_ssmb[(size_t)MM*DD];     // backward scan out
// activations: hi/lo pair (segment 3 == segment 1, not stored)
__device__ __align__(128) __nv_bfloat16 g_fm_h  [(size_t)MM*CC];
__device__ __align__(128) __nv_bfloat16 g_fm_l  [(size_t)MM*CC];
__device__ __align__(128) __nv_bfloat16 g_out1_h[(size_t)MM*CC];
__device__ __align__(128) __nv_bfloat16 g_out1_l[(size_t)MM*CC];
__device__ __align__(128) __nv_bfloat16 g_ssm_h [(size_t)MM*DD];
__device__ __align__(128) __nv_bfloat16 g_ssm_l [(size_t)MM*DD];
// weights stay 3x-expanded ([hi, hi, lo])
__device__ __align__(128) __nv_bfloat16 g_inw_e [(size_t)DIN2*KIN];
__device__ __align__(128) __nv_bfloat16 g_outw_e[(size_t)CC*KOUT];
__device__ __align__(128) __nv_bfloat16 g_mow_e [(size_t)CC*KIN];

// ---------------- helpers ----------------
__device__ __forceinline__ uint32_t smem_to_u32(const void* p) {
    uint32_t a;
    asm("{ .reg .u64 t; cvta.to.shared.u64 t, %1; cvt.u32.u64 %0, t; }" : "=r"(a) : "l"(p));
    return a;
}
#define SMEM_SWIZZLE_128B(off) ((off) ^ (((off) >> 3) & 0x70))

#define CP_ASYNC16(smem_u32, gptr) \
    asm volatile("cp.async.cg.shared.global [%0], [%1], 16;" \
                 :: "r"(smem_u32), "l"(__cvta_generic_to_global((const void*)(gptr))) : "memory")
#define CP_ASYNC_COMMIT() asm volatile("cp.async.commit_group;" ::: "memory")
#define CP_ASYNC_WAIT_2() asm volatile("cp.async.wait_group 2;" ::: "memory")

#define LDSM_X4(r0, r1, r2, r3, addr) \
    asm volatile("ldmatrix.sync.aligned.m8n8.x4.shared.b16 {%0,%1,%2,%3}, [%4];" \
                 : "=r"(r0), "=r"(r1), "=r"(r2), "=r"(r3) : "r"(addr))

#define MMA_BF16(d, a, b0, b1) \
    asm volatile("mma.sync.aligned.m16n8k16.row.col.f32.bf16.bf16.f32 " \
                 "{%0,%1,%2,%3}, {%4,%5,%6,%7}, {%8,%9}, {%0,%1,%2,%3};" \
                 : "+f"((d)[0]), "+f"((d)[1]), "+f"((d)[2]), "+f"((d)[3]) \
                 : "r"((a)[0]), "r"((a)[1]), "r"((a)[2]), "r"((a)[3]), \
                   "r"(b0), "r"(b1))

// ---------------- split-bf16 helpers ----------------
// Activations (A operand) segments: [hi, lo, hi] -> stored as hi/lo arrays.
// Weights     (B operand) segments: [hi, hi, lo] -> stored expanded.
// K'-dot = Ah*Bh + Al*Bh + Ah*Bl (drops only Al*Bl ~ 2^-18 relative)
__device__ __forceinline__ void split2(float v, __nv_bfloat16& h, __nv_bfloat16& l) {
    h = __float2bfloat16(v);
    l = __float2bfloat16(v - __bfloat162float(h));
}
__device__ __forceinline__ void split3w(float v, __nv_bfloat16* row, int K, int c) {
    __nv_bfloat16 h = __float2bfloat16(v);
    float lo = v - __bfloat162float(h);
    row[c] = h;
    row[K + c] = h;
    row[2 * K + c] = __float2bfloat16(lo);
}

// ---------------- 1. transpose + LayerNorm -> hi/lo fm ----------------
__global__ void ln_kernel(const float* __restrict__ x,
                          const float* __restrict__ w,
                          const float* __restrict__ b)
{
    int m  = blockIdx.x;
    int bb = m / LL, l = m % LL;
    const float* src = x + (size_t)bb * CC * LL + l;

    float v[8];
    float s = 0.f, s2 = 0.f;
#pragma unroll
    for (int k = 0; k < 8; k++) {
        int c = threadIdx.x + k * 256;
        float t = src[(size_t)c * LL];
        v[k] = t; s += t; s2 += t * t;
    }
    __shared__ float sred[64];
#pragma unroll
    for (int o = 16; o > 0; o >>= 1) {
        s  += __shfl_down_sync(0xffffffffu, s,  o);
        s2 += __shfl_down_sync(0xffffffffu, s2, o);
    }
    int wid = threadIdx.x >> 5, lane = threadIdx.x & 31;
    if (lane == 0) { sred[wid] = s; sred[32 + wid] = s2; }
    __syncthreads();
    if (threadIdx.x == 0) {
        float a = 0.f, a2 = 0.f;
#pragma unroll
        for (int i = 0; i < 8; i++) { a += sred[i]; a2 += sred[32 + i]; }
        sred[0] = a; sred[32] = a2;
    }
    __syncthreads();
    s = sred[0]; s2 = sred[32];

    float mu   = s * (1.f / CC);
    float var  = s2 * (1.f / CC) - mu * mu;
    float rstd = rsqrtf(var + 1e-5f);

    __nv_bfloat16* dh = g_fm_h + (size_t)m * CC;
    __nv_bfloat16* dl = g_fm_l + (size_t)m * CC;
#pragma unroll
    for (int k = 0; k < 8; k++) {
        int c = threadIdx.x + k * 256;
        float fv = (v[k] - mu) * rstd * w[c] + b[c];
        split2(fv, dh[c], dl[c]);
    }
}

// ---------------- weight split-convert ([hi, hi, lo]) ----------------
__global__ void wconv_kernel(const float* __restrict__ w, __nv_bfloat16* __restrict__ o,
                             int K, int total)
{
    int idx = blockIdx.x * blockDim.x + threadIdx.x;
    if (idx >= total) return;
    int r = idx / K, c = idx % K;
    split3w(w[idx], o + (size_t)r * 3 * K, K, c);
}

// ---------------- mma.sync bf16 GEMM: C = A(M x 3K)*B(N x 3K)^T ----------------
// A given as hi/lo arrays (stride K); segment s = j/(K/64): 0->hi, 1->lo, 2->hi.
// Byte-identical operand stream vs the old 3x-expanded layout.
// BM x BN block, BK=64, 4-stage cp.async (distance 2), single sync per iter,
// 8 warps (2m x 4n), ldmatrix fragments.
template <int BM, int BN, int EPI>
__global__ void __launch_bounds__(256) gemm_mma(
    const __nv_bfloat16* __restrict__ Ahi, const __nv_bfloat16* __restrict__ Alo,
    const __nv_bfloat16* __restrict__ B,
    int K, int Nout,
    const float* __restrict__ bias,
    const __nv_bfloat16* __restrict__ rhi, const __nv_bfloat16* __restrict__ rlo,
    float* __restrict__ Cf,
    __nv_bfloat16* __restrict__ Chi, __nv_bfloat16* __restrict__ Clo,
    const float* __restrict__ bn_rm, const float* __restrict__ bn_rv,
    const float* __restrict__ bn_w,  const float* __restrict__ bn_b)
{
    constexpr int S      = 4;
    constexpr int ABYTES = BM * 128;
    constexpr int BBYTES = BN * 128;
    constexpr int STAGE  = ABYTES + BBYTES;
    constexpr int MI     = BM / 32;
    constexpr int NT     = BN / 64;
    constexpr int NI     = BN / 32;
    constexpr int AITER  = BM / 32;
    constexpr int BITER  = BN / 32;

    extern __shared__ char smem[];
    uint32_t sb = smem_to_u32(smem);

    int tid = threadIdx.x, wid = tid >> 5, lane = tid & 31;
    int m0 = blockIdx.y * BM, n0 = blockIdx.x * BN;
    int wm0 = (wid & 1) * (BM / 2);
    int wn0 = (wid >> 1) * (BN / 4);

    int lrow8 = lane & 7;
    int g     = lane >> 3;
    int mg    = (g & 1) * 8;
    int kg    = (g >> 1) * 8;

    float acc[MI][NI][4];
#pragma unroll
    for (int i = 0; i < MI; i++)
#pragma unroll
        for (int j = 0; j < NI; j++)
#pragma unroll
            for (int q = 0; q < 4; q++) acc[i][j][q] = 0.f;

    const int t3 = K >> 6;          // chunks per segment
    const int T  = 3 * t3;
    const int Kb = 3 * K;           // B row stride (expanded weights)

    int lrow = tid >> 3;            // 0..31
    int lcol = tid & 7;             // 16B chunk col
    auto load = [&](int j) {
        uint32_t abase = sb + (j % S) * STAGE;
        uint32_t bbase = abase + ABYTES;
        int s = j / t3;
        const __nv_bfloat16* Ab = (s == 1) ? Alo : Ahi;
        int k0a = (j - s * t3) * 64;
        int k0b = j * 64;
#pragma unroll
        for (int c = 0; c < AITER; c++) {
            int row = lrow + c * 32;
            uint32_t soff = SMEM_SWIZZLE_128B((uint32_t)(row * 128 + lcol * 16));
            CP_ASYNC16(abase + soff, Ab + (size_t)(m0 + row) * K + k0a + lcol * 8);
        }
#pragma unroll
        for (int c = 0; c < BITER; c++) {
            int row = lrow + c * 32;
            uint32_t soff = SMEM_SWIZZLE_128B((uint32_t)(row * 128 + lcol * 16));
            CP_ASYNC16(bbase + soff, B + (size_t)(n0 + row) * Kb + k0b + lcol * 8);
        }
    };

    load(0); CP_ASYNC_COMMIT();
    load(1); CP_ASYNC_COMMIT();

    for (int i = 0; i < T; i++) {
        if (i + 2 < T) load(i + 2);
        CP_ASYNC_COMMIT();
        CP_ASYNC_WAIT_2();
        __syncthreads();
        // S=4, distance 2, single barrier: writes hit stage (i+2)%4, reads i%4.

        uint32_t abase = sb + (i % S) * STAGE;
        uint32_t bbase = abase + ABYTES;

#pragma unroll
        for (int kk = 0; kk < 4; kk++) {
            int coff = (kk * 16 + kg) * 2;
            uint32_t a[MI][4], b[NT][4];
#pragma unroll
            for (int mi = 0; mi < MI; mi++) {
                int row = wm0 + mi * 16 + lrow8 + mg;
                uint32_t ad = abase + SMEM_SWIZZLE_128B((uint32_t)(row * 128 + coff));
                LDSM_X4(a[mi][0], a[mi][1], a[mi][2], a[mi][3], ad);
            }
#pragma unroll
            for (int nt = 0; nt < NT; nt++) {
                int row = wn0 + nt * 16 + lrow8 + mg;
                uint32_t bd = bbase + SMEM_SWIZZLE_128B((uint32_t)(row * 128 + coff));
                LDSM_X4(b[nt][0], b[nt][1], b[nt][2], b[nt][3], bd);
            }
#pragma unroll
            for (int mi = 0; mi < MI; mi++) {
#pragma unroll
                for (int nt = 0; nt < NT; nt++) {
                    MMA_BF16(acc[mi][nt * 2 + 0], a[mi], b[nt][0], b[nt][2]);
                    MMA_BF16(acc[mi][nt * 2 + 1], a[mi], b[nt][1], b[nt][3]);
                }
            }
        }
    }

    // ---------------- epilogue (registers only) ----------------
    int qrow = lane >> 2;
    int qcol = (lane & 3) * 2;
#pragma unroll
    for (int mi = 0; mi < MI; mi++) {
#pragma unroll
        for (int ni = 0; ni < NI; ni++) {
#pragma unroll
            for (int h = 0; h < 2; h++) {
#pragma unroll
                for (int q = 0; q < 2; q++) {
                    int m = m0 + wm0 + mi * 16 + qrow + h * 8;
                    int n = n0 + wn0 + ni * 8 + qcol + q;
                    float v = acc[mi][ni][h * 2 + q] + bias[n];
                    if (EPI == 0) {
                        Cf[(size_t)m * Nout + n] = v;
                    } else if (EPI == 1) {
                        v += __bfloat162float(rhi[(size_t)m * CC + n])
                           + __bfloat162float(rlo[(size_t)m * CC + n]);
                        split2(v, Chi[(size_t)m * CC + n], Clo[(size_t)m * CC + n]);
                    } else {
                        float rs = rsqrtf(bn_rv[n] + 1e-5f);
                        v = (v - bn_rm[n]) * rs * bn_w[n] + bn_b[n];
                        v = fmaxf(v, 0.f);
                        int bb = m / LL, l = m - bb * LL;
                        Cf[((size_t)bb * CC + n) * LL + l] = v;
                    }
                }
            }
        }
    }
}

// ---------------- x_proj ----------------
__global__ void xproj_kernel(const float* __restrict__ xpw)
{
    int idx = blockIdx.x * blockDim.x + threadIdx.x;
    if (idx >= MM * NPROJ) return;
    int m = idx / NPROJ, j = idx % NPROJ;
    const float* xr = g_xz + (size_t)m * DIN2;
    const float* wr = xpw + j * DD;
    float acc = 0.f;
#pragma unroll 8
    for (int k = 0; k < DD; k++) acc += xr[k] * wr[k];
    g_xdbl[idx] = acc;
}

// ---------------- dt softplus ----------------
__global__ void dt_kernel(const float* __restrict__ dtw)
{
    int idx = blockIdx.x * blockDim.x + threadIdx.x;
    if (idx >= MM * DD) return;
    int m = idx / DD, d = idx % DD;
    const float* xd = g_xdbl + (size_t)m * NPROJ;
    float acc = 0.f;
#pragma unroll
    for (int r = 0; r < RR; r++) acc += xd[r] * dtw[d * RR + r];
    float sp = (acc > 20.f) ? acc : log1pf(__expf(acc));
    g_dts[idx] = sp;
}

// ---------------- bidirectional scan: fwd+bwd concurrent (128 blocks) ----------------
__global__ void scan_kernel(const float* __restrict__ A_logs,
                            const float* __restrict__ Ds)
{
    __shared__ float sB[LL][NN];
    __shared__ float sC[LL][NN];
    int b = blockIdx.x & 63;
    bool back = blockIdx.x >= 64;
    int d = threadIdx.x;

    for (int i = d; i < LL * 2 * NN; i += LL) {
        int l = i >> 5, j = i & 31;
        float v = g_xdbl[((size_t)(b * LL + l)) * NPROJ + RR + j];
        if (j < NN) sB[l][j] = v;
        else        sC[l][j - NN] = v;
    }
    __syncthreads();

    float Ar[NN];
#pragma unroll
    for (int n = 0; n < NN; n++) Ar[n] = -expf(A_logs[d * NN + n]);
    float Dd = Ds[d];

    float u[NN];
#pragma unroll
    for (int n = 0; n < NN; n++) u[n] = 0.f;

    float* dst = back ? g_ssmb : g_ssmf;
    int l0   = back ? LL - 1 : 0;
    int step = back ? -1 : 1;
    for (int t = 0; t < LL; t++) {
        int l = l0 + t * step;
        int m = b * LL + l;
        float dt = g_dts[(size_t)m * DD + d];
        float xv = g_xz [(size_t)m * DIN2 + d];
        float y = 0.f;
#pragma unroll
        for (int n = 0; n < NN; n++) {
            float a = __expf(dt * Ar[n]);
            u[n] = a * u[n] + dt * sB[l][n] * xv;
            y += u[n] * sC[l][n];
        }
        dst[(size_t)m * DD + d] = y + Dd * xv;
    }
}

// ---------------- gate: (fwd+bwd) * silu(z) -> hi/lo ssm ----------------
__global__ void gate_kernel()
{
    int idx = blockIdx.x * blockDim.x + threadIdx.x;
    if (idx >= MM * DD) return;
    int m = idx / DD, d = idx % DD;
    float tot = g_ssmf[idx] + g_ssmb[idx];
    float z = g_xz[(size_t)m * DIN2 + DD + d];
    float sig = 1.f / (1.f + __expf(-z));
    split2(tot * (z * sig), g_ssm_h[idx], g_ssm_l[idx]);
}

// ---------------- launch ----------------
extern "C" void kernel_launch(void* const* d_in, const int* in_sizes, int n_in,
                              void* d_out, int out_size)
{
    const float* feat_map = (const float*)d_in[0];
    const float* ln_w     = (const float*)d_in[1];
    const float* ln_b     = (const float*)d_in[2];
    const float* in_w     = (const float*)d_in[3];
    const float* in_b     = (const float*)d_in[4];
    const float* x_proj_w = (const float*)d_in[5];
    const float* dt_w     = (const float*)d_in[6];
    const float* A_logs   = (const float*)d_in[7];
    const float* Ds       = (const float*)d_in[8];
    const float* out_w    = (const float*)d_in[9];
    const float* out_b    = (const float*)d_in[10];
    const float* mo_w     = (const float*)d_in[11];
    const float* mo_b     = (const float*)d_in[12];
    const float* bn_w     = (const float*)d_in[13];
    const float* bn_b     = (const float*)d_in[14];
    const float* bn_rm    = (const float*)d_in[15];
    const float* bn_rv    = (const float*)d_in[16];
    float* out = (float*)d_out;

    __nv_bfloat16 *fm_h, *fm_l, *out1_h, *out1_l, *ssm_h, *ssm_l;
    __nv_bfloat16 *inw_e, *outw_e, *mow_e;
    float *xz;
    cudaGetSymbolAddress((void**)&fm_h,   g_fm_h);
    cudaGetSymbolAddress((void**)&fm_l,   g_fm_l);
    cudaGetSymbolAddress((void**)&out1_h, g_out1_h);
    cudaGetSymbolAddress((void**)&out1_l, g_out1_l);
    cudaGetSymbolAddress((void**)&ssm_h,  g_ssm_h);
    cudaGetSymbolAddress((void**)&ssm_l,  g_ssm_l);
    cudaGetSymbolAddress((void**)&inw_e,  g_inw_e);
    cudaGetSymbolAddress((void**)&outw_e, g_outw_e);
    cudaGetSymbolAddress((void**)&mow_e,  g_mow_e);
    cudaGetSymbolAddress((void**)&xz,     g_xz);

    const int SMEM_IN  = 4 * (128 + 128) * 128;   // 131072  (BM=128, BN=128)
    const int SMEM_BIG = 4 * (96 + 256) * 128;    // 180224  (BM=96,  BN=256)
    cudaFuncSetAttribute((gemm_mma<128, 128, 0>), cudaFuncAttributeMaxDynamicSharedMemorySize, SMEM_IN);
    cudaFuncSetAttribute((gemm_mma<96, 256, 1>),  cudaFuncAttributeMaxDynamicSharedMemorySize, SMEM_BIG);
    cudaFuncSetAttribute((gemm_mma<96, 256, 2>),  cudaFuncAttributeMaxDynamicSharedMemorySize, SMEM_BIG);

    // 1. transpose + LN -> fm hi/lo
    ln_kernel<<<MM, 256>>>(feat_map, ln_w, ln_b);

    // weight conversions ([hi, hi, lo])
    wconv_kernel<<<(DIN2 * CC + 255) / 256, 256>>>(in_w,  inw_e,  CC, DIN2 * CC);
    wconv_kernel<<<(CC * DD   + 255) / 256, 256>>>(out_w, outw_e, DD, CC * DD);
    wconv_kernel<<<(CC * CC   + 255) / 256, 256>>>(mo_w,  mow_e,  CC, CC * CC);

    // 2. in-projection: xz = fm @ in_w^T + in_b (fp32 out)
    gemm_mma<128, 128, 0><<<dim3(DIN2 / 128, MM / 128), 256, SMEM_IN>>>(
        fm_h, fm_l, inw_e, CC, DIN2, in_b, nullptr, nullptr, xz, nullptr, nullptr,
        nullptr, nullptr, nullptr, nullptr);

    // 3. x-proj + dt
    xproj_kernel<<<(MM * NPROJ + 255) / 256, 256>>>(x_proj_w);
    dt_kernel<<<(MM * DD) / 256, 256>>>(dt_w);

    // 4. scan (fwd+bwd concurrent) + gate -> ssm hi/lo
    scan_kernel<<<128, DD>>>(A_logs, Ds);
    gate_kernel<<<(MM * DD) / 256, 256>>>();

    // 5. out-projection + fm residual -> out1 hi/lo  (BM=96: 1024 CTAs)
    gemm_mma<96, 256, 1><<<dim3(CC / 256, MM / 96), 256, SMEM_BIG>>>(
        ssm_h, ssm_l, outw_e, DD, CC, out_b, fm_h, fm_l, nullptr, out1_h, out1_l,
        nullptr, nullptr, nullptr, nullptr);

    // 6. mixer GEMM + BN + ReLU + NCHW write  (BM=96: 1024 CTAs)
    gemm_mma<96, 256, 2><<<dim3(CC / 256, MM / 96), 256, SMEM_BIG>>>(
        out1_h, out1_l, mow_e, CC, CC, mo_b, nullptr, nullptr, out, nullptr, nullptr,
        bn_rm, bn_rv, bn_w, bn_b);
}

// round 15
// speedup vs baseline: 2.3778x; 1.1872x over previous
#include <cuda_runtime.h>
#include <cuda_bf16.h>
#include <cuda_fp16.h>
#include <cstdint>

// ---------------- problem constants ----------------
#define BSZ   64
#define CC    2048
#define LL    192
#define DIN2  384
#define DD    192
#define NN    16
#define RR    6
#define MM    (BSZ*LL)     // 12288
#define NPROJ 38
#define KIN   (3*CC)       // 6144 (expanded K for bf16-3 weights, C-side)
#define KOUT  (3*DD)       // 576  (expanded K for bf16-3 weights, D-side)

// ---------------- scratch ----------------
__device__ float g_xz  [(size_t)MM*DIN2];
__device__ float g_xdbl[(size_t)MM*NPROJ];
__device__ float g_dts [(size_t)MM*DD];
__device__ float g_ssmf[(size_t)MM*DD];
__device__ float g_ssmb[(size_t)MM*DD];
// bf16-3 activations (hi/lo; 3rd segment == 1st)
__device__ __align__(128) __nv_bfloat16 g_fm_h  [(size_t)MM*CC];
__device__ __align__(128) __nv_bfloat16 g_fm_l  [(size_t)MM*CC];
__device__ __align__(128) __nv_bfloat16 g_ssm_h [(size_t)MM*DD];
__device__ __align__(128) __nv_bfloat16 g_ssm_l [(size_t)MM*DD];
// fp16-2 mixer activations (hi/lo)
__device__ __align__(128) __half g_out1_h[(size_t)MM*CC];
__device__ __align__(128) __half g_out1_l[(size_t)MM*CC];
// weights: bf16 expanded ([hi, hi, lo]) for in/out-proj; fp16 plain for mixer
__device__ __align__(128) __nv_bfloat16 g_inw_e [(size_t)DIN2*KIN];
__device__ __align__(128) __nv_bfloat16 g_outw_e[(size_t)CC*KOUT];
__device__ __align__(128) __half        g_mow_h [(size_t)CC*CC];

// ---------------- helpers ----------------
__device__ __forceinline__ uint32_t smem_to_u32(const void* p) {
    uint32_t a;
    asm("{ .reg .u64 t; cvta.to.shared.u64 t, %1; cvt.u32.u64 %0, t; }" : "=r"(a) : "l"(p));
    return a;
}
#define SMEM_SWIZZLE_128B(off) ((off) ^ (((off) >> 3) & 0x70))

#define CP_ASYNC16(smem_u32, gptr) \
    asm volatile("cp.async.cg.shared.global [%0], [%1], 16;" \
                 :: "r"(smem_u32), "l"(__cvta_generic_to_global((const void*)(gptr))) : "memory")
#define CP_ASYNC_COMMIT() asm volatile("cp.async.commit_group;" ::: "memory")
#define CP_ASYNC_WAIT_2() asm volatile("cp.async.wait_group 2;" ::: "memory")

#define LDSM_X4(r0, r1, r2, r3, addr) \
    asm volatile("ldmatrix.sync.aligned.m8n8.x4.shared.b16 {%0,%1,%2,%3}, [%4];" \
                 : "=r"(r0), "=r"(r1), "=r"(r2), "=r"(r3) : "r"(addr))

#define MMA_BF16(d, a, b0, b1) \
    asm volatile("mma.sync.aligned.m16n8k16.row.col.f32.bf16.bf16.f32 " \
                 "{%0,%1,%2,%3}, {%4,%5,%6,%7}, {%8,%9}, {%0,%1,%2,%3};" \
                 : "+f"((d)[0]), "+f"((d)[1]), "+f"((d)[2]), "+f"((d)[3]) \
                 : "r"((a)[0]), "r"((a)[1]), "r"((a)[2]), "r"((a)[3]), \
                   "r"(b0), "r"(b1))
#define MMA_F16(d, a, b0, b1) \
    asm volatile("mma.sync.aligned.m16n8k16.row.col.f32.f16.f16.f32 " \
                 "{%0,%1,%2,%3}, {%4,%5,%6,%7}, {%8,%9}, {%0,%1,%2,%3};" \
                 : "+f"((d)[0]), "+f"((d)[1]), "+f"((d)[2]), "+f"((d)[3]) \
                 : "r"((a)[0]), "r"((a)[1]), "r"((a)[2]), "r"((a)[3]), \
                   "r"(b0), "r"(b1))

// ---------------- split helpers ----------------
// bf16-3: A segs [hi, lo, hi], W segs [hi, hi, lo] -> AhBh + AlBh + AhBl
// fp16-2 (mixer): A segs [hi, lo], W segs [hi, hi(same array)] -> AhBh + AlBh
__device__ __forceinline__ void split2(float v, __nv_bfloat16& h, __nv_bfloat16& l) {
    h = __float2bfloat16(v);
    l = __float2bfloat16(v - __bfloat162float(h));
}
__device__ __forceinline__ void split2h(float v, __half& h, __half& l) {
    h = __float2half_rn(v);
    l = __float2half_rn(v - __half2float(h));
}
__device__ __forceinline__ void split3w(float v, __nv_bfloat16* row, int K, int c) {
    __nv_bfloat16 h = __float2bfloat16(v);
    float lo = v - __bfloat162float(h);
    row[c] = h;
    row[K + c] = h;
    row[2 * K + c] = __float2bfloat16(lo);
}

// ---------------- 1. transpose + LayerNorm -> hi/lo fm ----------------
__global__ void ln_kernel(const float* __restrict__ x,
                          const float* __restrict__ w,
                          const float* __restrict__ b)
{
    int m  = blockIdx.x;
    int bb = m / LL, l = m % LL;
    const float* src = x + (size_t)bb * CC * LL + l;

    float v[8];
    float s = 0.f, s2 = 0.f;
#pragma unroll
    for (int k = 0; k < 8; k++) {
        int c = threadIdx.x + k * 256;
        float t = src[(size_t)c * LL];
        v[k] = t; s += t; s2 += t * t;
    }
    __shared__ float sred[64];
#pragma unroll
    for (int o = 16; o > 0; o >>= 1) {
        s  += __shfl_down_sync(0xffffffffu, s,  o);
        s2 += __shfl_down_sync(0xffffffffu, s2, o);
    }
    int wid = threadIdx.x >> 5, lane = threadIdx.x & 31;
    if (lane == 0) { sred[wid] = s; sred[32 + wid] = s2; }
    __syncthreads();
    if (threadIdx.x == 0) {
        float a = 0.f, a2 = 0.f;
#pragma unroll
        for (int i = 0; i < 8; i++) { a += sred[i]; a2 += sred[32 + i]; }
        sred[0] = a; sred[32] = a2;
    }
    __syncthreads();
    s = sred[0]; s2 = sred[32];

    float mu   = s * (1.f / CC);
    float var  = s2 * (1.f / CC) - mu * mu;
    float rstd = rsqrtf(var + 1e-5f);

    __nv_bfloat16* dh = g_fm_h + (size_t)m * CC;
    __nv_bfloat16* dl = g_fm_l + (size_t)m * CC;
#pragma unroll
    for (int k = 0; k < 8; k++) {
        int c = threadIdx.x + k * 256;
        float fv = (v[k] - mu) * rstd * w[c] + b[c];
        split2(fv, dh[c], dl[c]);
    }
}

// ---------------- weight conversions ----------------
__global__ void wconv_kernel(const float* __restrict__ w, __nv_bfloat16* __restrict__ o,
                             int K, int total)
{
    int idx = blockIdx.x * blockDim.x + threadIdx.x;
    if (idx >= total) return;
    int r = idx / K, c = idx % K;
    split3w(w[idx], o + (size_t)r * 3 * K, K, c);
}
__global__ void wconvh_kernel(const float* __restrict__ w, __half* __restrict__ o, int total)
{
    int idx = blockIdx.x * blockDim.x + threadIdx.x;
    if (idx >= total) return;
    o[idx] = __float2half_rn(w[idx]);
}

// ---------------- mma.sync GEMM: C = A(M x SEGS*K) * B(N x SEGS*K)^T ----------------
// SEGS=3 (bf16): A segs hi,lo,hi (two arrays); B expanded [hi,hi,lo], stride 3K.
// SEGS=2 (fp16): A segs hi,lo; B single array read for BOTH segments, stride K.
// BM x BN block, BK=64, 4-stage cp.async (distance 2), single sync per iter,
// 8 warps (2m x 4n), ldmatrix fragments.
template <int BM, int BN, int SEGS, int FP16, int EPI>
__global__ void __launch_bounds__(256) gemm_mma(
    const __nv_bfloat16* __restrict__ Ahi, const __nv_bfloat16* __restrict__ Alo,
    const __nv_bfloat16* __restrict__ B,
    int K, int Nout,
    const float* __restrict__ bias,
    const __nv_bfloat16* __restrict__ rhi, const __nv_bfloat16* __restrict__ rlo,
    float* __restrict__ Cf,
    __half* __restrict__ Chi, __half* __restrict__ Clo,
    const float* __restrict__ bn_rm, const float* __restrict__ bn_rv,
    const float* __restrict__ bn_w,  const float* __restrict__ bn_b)
{
    constexpr int S      = 4;
    constexpr int ABYTES = BM * 128;
    constexpr int BBYTES = BN * 128;
    constexpr int STAGE  = ABYTES + BBYTES;
    constexpr int MI     = BM / 32;
    constexpr int NT     = BN / 64;
    constexpr int NI     = BN / 32;
    constexpr int AITER  = BM / 32;
    constexpr int BITER  = BN / 32;

    extern __shared__ char smem[];
    uint32_t sb = smem_to_u32(smem);

    int tid = threadIdx.x, wid = tid >> 5, lane = tid & 31;
    int m0 = blockIdx.y * BM, n0 = blockIdx.x * BN;
    int wm0 = (wid & 1) * (BM / 2);
    int wn0 = (wid >> 1) * (BN / 4);

    int lrow8 = lane & 7;
    int g     = lane >> 3;
    int mg    = (g & 1) * 8;
    int kg    = (g >> 1) * 8;

    float acc[MI][NI][4];
#pragma unroll
    for (int i = 0; i < MI; i++)
#pragma unroll
        for (int j = 0; j < NI; j++)
#pragma unroll
            for (int q = 0; q < 4; q++) acc[i][j][q] = 0.f;

    const int t3 = K >> 6;            // chunks per segment
    const int T  = SEGS * t3;
    const int Kb = (SEGS == 3) ? 3 * K : K;   // B row stride

    int lrow = tid >> 3;              // 0..31
    int lcol = tid & 7;               // 16B chunk col
    auto load = [&](int j) {
        uint32_t abase = sb + (j % S) * STAGE;
        uint32_t bbase = abase + ABYTES;
        int s = j / t3;
        const __nv_bfloat16* Ab =
            (SEGS == 3) ? ((s == 1) ? Alo : Ahi) : ((s == 0) ? Ahi : Alo);
        int k0a = (j - s * t3) * 64;
        int k0b = (SEGS == 3) ? j * 64 : k0a;   // SEGS=2: both segments read same B cols
#pragma unroll
        for (int c = 0; c < AITER; c++) {
            int row = lrow + c * 32;
            uint32_t soff = SMEM_SWIZZLE_128B((uint32_t)(row * 128 + lcol * 16));
            CP_ASYNC16(abase + soff, Ab + (size_t)(m0 + row) * K + k0a + lcol * 8);
        }
#pragma unroll
        for (int c = 0; c < BITER; c++) {
            int row = lrow + c * 32;
            uint32_t soff = SMEM_SWIZZLE_128B((uint32_t)(row * 128 + lcol * 16));
            CP_ASYNC16(bbase + soff, B + (size_t)(n0 + row) * Kb + k0b + lcol * 8);
        }
    };

    load(0); CP_ASYNC_COMMIT();
    load(1); CP_ASYNC_COMMIT();

    for (int i = 0; i < T; i++) {
        if (i + 2 < T) load(i + 2);
        CP_ASYNC_COMMIT();
        CP_ASYNC_WAIT_2();
        __syncthreads();
        // S=4, distance 2, single barrier: writes hit stage (i+2)%4, reads i%4.

        uint32_t abase = sb + (i % S) * STAGE;
        uint32_t bbase = abase + ABYTES;

#pragma unroll
        for (int kk = 0; kk < 4; kk++) {
            int coff = (kk * 16 + kg) * 2;
            uint32_t a[MI][4], b[NT][4];
#pragma unroll
            for (int mi = 0; mi < MI; mi++) {
                int row = wm0 + mi * 16 + lrow8 + mg;
                uint32_t ad = abase + SMEM_SWIZZLE_128B((uint32_t)(row * 128 + coff));
                LDSM_X4(a[mi][0], a[mi][1], a[mi][2], a[mi][3], ad);
            }
#pragma unroll
            for (int nt = 0; nt < NT; nt++) {
                int row = wn0 + nt * 16 + lrow8 + mg;
                uint32_t bd = bbase + SMEM_SWIZZLE_128B((uint32_t)(row * 128 + coff));
                LDSM_X4(b[nt][0], b[nt][1], b[nt][2], b[nt][3], bd);
            }
#pragma unroll
            for (int mi = 0; mi < MI; mi++) {
#pragma unroll
                for (int nt = 0; nt < NT; nt++) {
                    if (FP16) {
                        MMA_F16(acc[mi][nt * 2 + 0], a[mi], b[nt][0], b[nt][2]);
                        MMA_F16(acc[mi][nt * 2 + 1], a[mi], b[nt][1], b[nt][3]);
                    } else {
                        MMA_BF16(acc[mi][nt * 2 + 0], a[mi], b[nt][0], b[nt][2]);
                        MMA_BF16(acc[mi][nt * 2 + 1], a[mi], b[nt][1], b[nt][3]);
                    }
                }
            }
        }
    }

    // ---------------- epilogue (registers only) ----------------
    int qrow = lane >> 2;
    int qcol = (lane & 3) * 2;
#pragma unroll
    for (int mi = 0; mi < MI; mi++) {
#pragma unroll
        for (int ni = 0; ni < NI; ni++) {
#pragma unroll
            for (int h = 0; h < 2; h++) {
#pragma unroll
                for (int q = 0; q < 2; q++) {
                    int m = m0 + wm0 + mi * 16 + qrow + h * 8;
                    int n = n0 + wn0 + ni * 8 + qcol + q;
                    float v = acc[mi][ni][h * 2 + q] + bias[n];
                    if (EPI == 0) {
                        Cf[(size_t)m * Nout + n] = v;
                    } else if (EPI == 1) {
                        v += __bfloat162float(rhi[(size_t)m * CC + n])
                           + __bfloat162float(rlo[(size_t)m * CC + n]);
                        split2h(v, Chi[(size_t)m * CC + n], Clo[(size_t)m * CC + n]);
                    } else {
                        float rs = rsqrtf(bn_rv[n] + 1e-5f);
                        v = (v - bn_rm[n]) * rs * bn_w[n] + bn_b[n];
                        v = fmaxf(v, 0.f);
                        int bb = m / LL, l = m - bb * LL;
                        Cf[((size_t)bb * CC + n) * LL + l] = v;
                    }
                }
            }
        }
    }
}

// ---------------- x_proj ----------------
__global__ void xproj_kernel(const float* __restrict__ xpw)
{
    int idx = blockIdx.x * blockDim.x + threadIdx.x;
    if (idx >= MM * NPROJ) return;
    int m = idx / NPROJ, j = idx % NPROJ;
    const float* xr = g_xz + (size_t)m * DIN2;
    const float* wr = xpw + j * DD;
    float acc = 0.f;
#pragma unroll 8
    for (int k = 0; k < DD; k++) acc += xr[k] * wr[k];
    g_xdbl[idx] = acc;
}

// ---------------- dt softplus ----------------
__global__ void dt_kernel(const float* __restrict__ dtw)
{
    int idx = blockIdx.x * blockDim.x + threadIdx.x;
    if (idx >= MM * DD) return;
    int m = idx / DD, d = idx % DD;
    const float* xd = g_xdbl + (size_t)m * NPROJ;
    float acc = 0.f;
#pragma unroll
    for (int r = 0; r < RR; r++) acc += xd[r] * dtw[d * RR + r];
    float sp = (acc > 20.f) ? acc : log1pf(__expf(acc));
    g_dts[idx] = sp;
}

// ---------------- bidirectional scan: fwd+bwd concurrent (128 blocks) ----------------
__global__ void scan_kernel(const float* __restrict__ A_logs,
                            const float* __restrict__ Ds)
{
    __shared__ float sB[LL][NN];
    __shared__ float sC[LL][NN];
    int b = blockIdx.x & 63;
    bool back = blockIdx.x >= 64;
    int d = threadIdx.x;

    for (int i = d; i < LL * 2 * NN; i += LL) {
        int l = i >> 5, j = i & 31;
        float v = g_xdbl[((size_t)(b * LL + l)) * NPROJ + RR + j];
        if (j < NN) sB[l][j] = v;
        else        sC[l][j - NN] = v;
    }
    __syncthreads();

    float Ar[NN];
#pragma unroll
    for (int n = 0; n < NN; n++) Ar[n] = -expf(A_logs[d * NN + n]);
    float Dd = Ds[d];

    float u[NN];
#pragma unroll
    for (int n = 0; n < NN; n++) u[n] = 0.f;

    float* dst = back ? g_ssmb : g_ssmf;
    int l0   = back ? LL - 1 : 0;
    int step = back ? -1 : 1;
    for (int t = 0; t < LL; t++) {
        int l = l0 + t * step;
        int m = b * LL + l;
        float dt = g_dts[(size_t)m * DD + d];
        float xv = g_xz [(size_t)m * DIN2 + d];
        float y = 0.f;
#pragma unroll
        for (int n = 0; n < NN; n++) {
            float a = __expf(dt * Ar[n]);
            u[n] = a * u[n] + dt * sB[l][n] * xv;
            y += u[n] * sC[l][n];
        }
        dst[(size_t)m * DD + d] = y + Dd * xv;
    }
}

// ---------------- gate: (fwd+bwd) * silu(z) -> hi/lo ssm (bf16) ----------------
__global__ void gate_kernel()
{
    int idx = blockIdx.x * blockDim.x + threadIdx.x;
    if (idx >= MM * DD) return;
    int m = idx / DD, d = idx % DD;
    float tot = g_ssmf[idx] + g_ssmb[idx];
    float z = g_xz[(size_t)m * DIN2 + DD + d];
    float sig = 1.f / (1.f + __expf(-z));
    split2(tot * (z * sig), g_ssm_h[idx], g_ssm_l[idx]);
}

// ---------------- launch ----------------
extern "C" void kernel_launch(void* const* d_in, const int* in_sizes, int n_in,
                              void* d_out, int out_size)
{
    const float* feat_map = (const float*)d_in[0];
    const float* ln_w     = (const float*)d_in[1];
    const float* ln_b     = (const float*)d_in[2];
    const float* in_w     = (const float*)d_in[3];
    const float* in_b     = (const float*)d_in[4];
    const float* x_proj_w = (const float*)d_in[5];
    const float* dt_w     = (const float*)d_in[6];
    const float* A_logs   = (const float*)d_in[7];
    const float* Ds       = (const float*)d_in[8];
    const float* out_w    = (const float*)d_in[9];
    const float* out_b    = (const float*)d_in[10];
    const float* mo_w     = (const float*)d_in[11];
    const float* mo_b     = (const float*)d_in[12];
    const float* bn_w     = (const float*)d_in[13];
    const float* bn_b     = (const float*)d_in[14];
    const float* bn_rm    = (const float*)d_in[15];
    const float* bn_rv    = (const float*)d_in[16];
    float* out = (float*)d_out;

    __nv_bfloat16 *fm_h, *fm_l, *ssm_h, *ssm_l, *inw_e, *outw_e;
    __half *out1_h, *out1_l, *mow_h;
    float *xz;
    cudaGetSymbolAddress((void**)&fm_h,   g_fm_h);
    cudaGetSymbolAddress((void**)&fm_l,   g_fm_l);
    cudaGetSymbolAddress((void**)&ssm_h,  g_ssm_h);
    cudaGetSymbolAddress((void**)&ssm_l,  g_ssm_l);
    cudaGetSymbolAddress((void**)&out1_h, g_out1_h);
    cudaGetSymbolAddress((void**)&out1_l, g_out1_l);
    cudaGetSymbolAddress((void**)&inw_e,  g_inw_e);
    cudaGetSymbolAddress((void**)&outw_e, g_outw_e);
    cudaGetSymbolAddress((void**)&mow_h,  g_mow_h);
    cudaGetSymbolAddress((void**)&xz,     g_xz);

    const int SMEM_IN  = 4 * (128 + 128) * 128;   // 131072  (BM=128, BN=128)
    const int SMEM_BIG = 4 * (96 + 256) * 128;    // 180224  (BM=96,  BN=256)
    cudaFuncSetAttribute((gemm_mma<128, 128, 3, 0, 0>), cudaFuncAttributeMaxDynamicSharedMemorySize, SMEM_IN);
    cudaFuncSetAttribute((gemm_mma<96, 256, 3, 0, 1>),  cudaFuncAttributeMaxDynamicSharedMemorySize, SMEM_BIG);
    cudaFuncSetAttribute((gemm_mma<96, 256, 2, 1, 2>),  cudaFuncAttributeMaxDynamicSharedMemorySize, SMEM_BIG);

    // 1. transpose + LN -> fm hi/lo (bf16)
    ln_kernel<<<MM, 256>>>(feat_map, ln_w, ln_b);

    // weight conversions
    wconv_kernel<<<(DIN2 * CC + 255) / 256, 256>>>(in_w,  inw_e,  CC, DIN2 * CC);
    wconv_kernel<<<(CC * DD   + 255) / 256, 256>>>(out_w, outw_e, DD, CC * DD);
    wconvh_kernel<<<(CC * CC + 255) / 256, 256>>>(mo_w, mow_h, CC * CC);

    // 2. in-projection (bf16-3): xz = fm @ in_w^T + in_b
    gemm_mma<128, 128, 3, 0, 0><<<dim3(DIN2 / 128, MM / 128), 256, SMEM_IN>>>(
        fm_h, fm_l, inw_e, CC, DIN2, in_b, nullptr, nullptr, xz, nullptr, nullptr,
        nullptr, nullptr, nullptr, nullptr);

    // 3. x-proj + dt
    xproj_kernel<<<(MM * NPROJ + 255) / 256, 256>>>(x_proj_w);
    dt_kernel<<<(MM * DD) / 256, 256>>>(dt_w);

    // 4. scan (fwd+bwd concurrent) + gate -> ssm hi/lo (bf16)
    scan_kernel<<<128, DD>>>(A_logs, Ds);
    gate_kernel<<<(MM * DD) / 256, 256>>>();

    // 5. out-projection (bf16-3) + fm residual -> out1 hi/lo (fp16)
    gemm_mma<96, 256, 3, 0, 1><<<dim3(CC / 256, MM / 96), 256, SMEM_BIG>>>(
        ssm_h, ssm_l, outw_e, DD, CC, out_b, fm_h, fm_l, nullptr, out1_h, out1_l,
        nullptr, nullptr, nullptr, nullptr);

    // 6. mixer GEMM (fp16-2, K'=2K) + BN + ReLU + NCHW write
    gemm_mma<96, 256, 2, 1, 2><<<dim3(CC / 256, MM / 96), 256, SMEM_BIG>>>(
        (const __nv_bfloat16*)out1_h, (const __nv_bfloat16*)out1_l,
        (const __nv_bfloat16*)mow_h, CC, CC, mo_b, nullptr, nullptr, out, nullptr, nullptr,
        bn_rm, bn_rv, bn_w, bn_b);
}

// round 16
// speedup vs baseline: 2.4777x; 1.0420x over previous
#include <cuda_runtime.h>
#include <cuda_bf16.h>
#include <cuda_fp16.h>
#include <cstdint>

// ---------------- problem constants ----------------
#define BSZ   64
#define CC    2048
#define LL    192
#define DIN2  384
#define DD    192
#define NN    16
#define RR    6
#define MM    (BSZ*LL)     // 12288
#define NPROJ 38
#define KIN   (3*CC)       // 6144 (expanded K for bf16-3 weights, C-side)

// ---------------- scratch ----------------
__device__ float g_xz  [(size_t)MM*DIN2];
__device__ float g_xdbl[(size_t)MM*NPROJ];
__device__ float g_dts [(size_t)MM*DD];
__device__ float g_ssmf[(size_t)MM*DD];
__device__ float g_ssmb[(size_t)MM*DD];
// bf16-3 activations (hi/lo; 3rd segment == 1st)
__device__ __align__(128) __nv_bfloat16 g_fm_h  [(size_t)MM*CC];
__device__ __align__(128) __nv_bfloat16 g_fm_l  [(size_t)MM*CC];
// fp16-2 activations
__device__ __align__(128) __half g_ssm_h [(size_t)MM*DD];
__device__ __align__(128) __half g_ssm_l [(size_t)MM*DD];
__device__ __align__(128) __half g_out1_h[(size_t)MM*CC];
__device__ __align__(128) __half g_out1_l[(size_t)MM*CC];
// weights: bf16 expanded ([hi, hi, lo]) for in-proj; plain fp16 for out-proj + mixer
__device__ __align__(128) __nv_bfloat16 g_inw_e [(size_t)DIN2*KIN];
__device__ __align__(128) __half        g_outw_h[(size_t)CC*DD];
__device__ __align__(128) __half        g_mow_h [(size_t)CC*CC];

// ---------------- helpers ----------------
__device__ __forceinline__ uint32_t smem_to_u32(const void* p) {
    uint32_t a;
    asm("{ .reg .u64 t; cvta.to.shared.u64 t, %1; cvt.u32.u64 %0, t; }" : "=r"(a) : "l"(p));
    return a;
}
#define SMEM_SWIZZLE_128B(off) ((off) ^ (((off) >> 3) & 0x70))

#define CP_ASYNC16(smem_u32, gptr) \
    asm volatile("cp.async.cg.shared.global [%0], [%1], 16;" \
                 :: "r"(smem_u32), "l"(__cvta_generic_to_global((const void*)(gptr))) : "memory")
#define CP_ASYNC_COMMIT() asm volatile("cp.async.commit_group;" ::: "memory")
#define CP_ASYNC_WAIT_2() asm volatile("cp.async.wait_group 2;" ::: "memory")

#define LDSM_X4(r0, r1, r2, r3, addr) \
    asm volatile("ldmatrix.sync.aligned.m8n8.x4.shared.b16 {%0,%1,%2,%3}, [%4];" \
                 : "=r"(r0), "=r"(r1), "=r"(r2), "=r"(r3) : "r"(addr))

#define MMA_BF16(d, a, b0, b1) \
    asm volatile("mma.sync.aligned.m16n8k16.row.col.f32.bf16.bf16.f32 " \
                 "{%0,%1,%2,%3}, {%4,%5,%6,%7}, {%8,%9}, {%0,%1,%2,%3};" \
                 : "+f"((d)[0]), "+f"((d)[1]), "+f"((d)[2]), "+f"((d)[3]) \
                 : "r"((a)[0]), "r"((a)[1]), "r"((a)[2]), "r"((a)[3]), \
                   "r"(b0), "r"(b1))
#define MMA_F16(d, a, b0, b1) \
    asm volatile("mma.sync.aligned.m16n8k16.row.col.f32.f16.f16.f32 " \
                 "{%0,%1,%2,%3}, {%4,%5,%6,%7}, {%8,%9}, {%0,%1,%2,%3};" \
                 : "+f"((d)[0]), "+f"((d)[1]), "+f"((d)[2]), "+f"((d)[3]) \
                 : "r"((a)[0]), "r"((a)[1]), "r"((a)[2]), "r"((a)[3]), \
                   "r"(b0), "r"(b1))

// ---------------- split helpers ----------------
// bf16-3: A segs [hi, lo, hi], W segs [hi, hi, lo] -> AhBh + AlBh + AhBl
// fp16-2: A segs [hi, lo], W single array read for both segs -> AhBh + AlBh
__device__ __forceinline__ void split2(float v, __nv_bfloat16& h, __nv_bfloat16& l) {
    h = __float2bfloat16(v);
    l = __float2bfloat16(v - __bfloat162float(h));
}
__device__ __forceinline__ void split2h(float v, __half& h, __half& l) {
    h = __float2half_rn(v);
    l = __float2half_rn(v - __half2float(h));
}
__device__ __forceinline__ void split3w(float v, __nv_bfloat16* row, int K, int c) {
    __nv_bfloat16 h = __float2bfloat16(v);
    float lo = v - __bfloat162float(h);
    row[c] = h;
    row[K + c] = h;
    row[2 * K + c] = __float2bfloat16(lo);
}

// ---------------- 1. transpose + LayerNorm -> hi/lo fm ----------------
__global__ void ln_kernel(const float* __restrict__ x,
                          const float* __restrict__ w,
                          const float* __restrict__ b)
{
    int m  = blockIdx.x;
    int bb = m / LL, l = m % LL;
    const float* src = x + (size_t)bb * CC * LL + l;

    float v[8];
    float s = 0.f, s2 = 0.f;
#pragma unroll
    for (int k = 0; k < 8; k++) {
        int c = threadIdx.x + k * 256;
        float t = src[(size_t)c * LL];
        v[k] = t; s += t; s2 += t * t;
    }
    __shared__ float sred[64];
#pragma unroll
    for (int o = 16; o > 0; o >>= 1) {
        s  += __shfl_down_sync(0xffffffffu, s,  o);
        s2 += __shfl_down_sync(0xffffffffu, s2, o);
    }
    int wid = threadIdx.x >> 5, lane = threadIdx.x & 31;
    if (lane == 0) { sred[wid] = s; sred[32 + wid] = s2; }
    __syncthreads();
    if (threadIdx.x == 0) {
        float a = 0.f, a2 = 0.f;
#pragma unroll
        for (int i = 0; i < 8; i++) { a += sred[i]; a2 += sred[32 + i]; }
        sred[0] = a; sred[32] = a2;
    }
    __syncthreads();
    s = sred[0]; s2 = sred[32];

    float mu   = s * (1.f / CC);
    float var  = s2 * (1.f / CC) - mu * mu;
    float rstd = rsqrtf(var + 1e-5f);

    __nv_bfloat16* dh = g_fm_h + (size_t)m * CC;
    __nv_bfloat16* dl = g_fm_l + (size_t)m * CC;
#pragma unroll
    for (int k = 0; k < 8; k++) {
        int c = threadIdx.x + k * 256;
        float fv = (v[k] - mu) * rstd * w[c] + b[c];
        split2(fv, dh[c], dl[c]);
    }
}

// ---------------- weight conversions ----------------
__global__ void wconv_kernel(const float* __restrict__ w, __nv_bfloat16* __restrict__ o,
                             int K, int total)
{
    int idx = blockIdx.x * blockDim.x + threadIdx.x;
    if (idx >= total) return;
    int r = idx / K, c = idx % K;
    split3w(w[idx], o + (size_t)r * 3 * K, K, c);
}
__global__ void wconvh_kernel(const float* __restrict__ w, __half* __restrict__ o, int total)
{
    int idx = blockIdx.x * blockDim.x + threadIdx.x;
    if (idx >= total) return;
    o[idx] = __float2half_rn(w[idx]);
}

// ---------------- mma.sync GEMM: C = A(M x SEGS*K) * B(N x SEGS*K)^T ----------------
// SEGS=3 (bf16): A segs hi,lo,hi (two arrays); B expanded [hi,hi,lo], stride 3K.
// SEGS=2 (fp16): A segs hi,lo; B single array read for BOTH segments, stride K.
template <int BM, int BN, int SEGS, int FP16, int EPI>
__global__ void __launch_bounds__(256) gemm_mma(
    const __nv_bfloat16* __restrict__ Ahi, const __nv_bfloat16* __restrict__ Alo,
    const __nv_bfloat16* __restrict__ B,
    int K, int Nout,
    const float* __restrict__ bias,
    const __nv_bfloat16* __restrict__ rhi, const __nv_bfloat16* __restrict__ rlo,
    float* __restrict__ Cf,
    __half* __restrict__ Chi, __half* __restrict__ Clo,
    const float* __restrict__ bn_rm, const float* __restrict__ bn_rv,
    const float* __restrict__ bn_w,  const float* __restrict__ bn_b)
{
    constexpr int S      = 4;
    constexpr int ABYTES = BM * 128;
    constexpr int BBYTES = BN * 128;
    constexpr int STAGE  = ABYTES + BBYTES;
    constexpr int MI     = BM / 32;
    constexpr int NT     = BN / 64;
    constexpr int NI     = BN / 32;
    constexpr int AITER  = BM / 32;
    constexpr int BITER  = BN / 32;

    extern __shared__ char smem[];
    uint32_t sb = smem_to_u32(smem);

    int tid = threadIdx.x, wid = tid >> 5, lane = tid & 31;
    int m0 = blockIdx.y * BM, n0 = blockIdx.x * BN;
    int wm0 = (wid & 1) * (BM / 2);
    int wn0 = (wid >> 1) * (BN / 4);

    int lrow8 = lane & 7;
    int g     = lane >> 3;
    int mg    = (g & 1) * 8;
    int kg    = (g >> 1) * 8;

    float acc[MI][NI][4];
#pragma unroll
    for (int i = 0; i < MI; i++)
#pragma unroll
        for (int j = 0; j < NI; j++)
#pragma unroll
            for (int q = 0; q < 4; q++) acc[i][j][q] = 0.f;

    const int t3 = K >> 6;
    const int T  = SEGS * t3;
    const int Kb = (SEGS == 3) ? 3 * K : K;

    int lrow = tid >> 3;
    int lcol = tid & 7;
    auto load = [&](int j) {
        uint32_t abase = sb + (j % S) * STAGE;
        uint32_t bbase = abase + ABYTES;
        int s = j / t3;
        const __nv_bfloat16* Ab =
            (SEGS == 3) ? ((s == 1) ? Alo : Ahi) : ((s == 0) ? Ahi : Alo);
        int k0a = (j - s * t3) * 64;
        int k0b = (SEGS == 3) ? j * 64 : k0a;
#pragma unroll
        for (int c = 0; c < AITER; c++) {
            int row = lrow + c * 32;
            uint32_t soff = SMEM_SWIZZLE_128B((uint32_t)(row * 128 + lcol * 16));
            CP_ASYNC16(abase + soff, Ab + (size_t)(m0 + row) * K + k0a + lcol * 8);
        }
#pragma unroll
        for (int c = 0; c < BITER; c++) {
            int row = lrow + c * 32;
            uint32_t soff = SMEM_SWIZZLE_128B((uint32_t)(row * 128 + lcol * 16));
            CP_ASYNC16(bbase + soff, B + (size_t)(n0 + row) * Kb + k0b + lcol * 8);
        }
    };

    load(0); CP_ASYNC_COMMIT();
    load(1); CP_ASYNC_COMMIT();

    for (int i = 0; i < T; i++) {
        if (i + 2 < T) load(i + 2);
        CP_ASYNC_COMMIT();
        CP_ASYNC_WAIT_2();
        __syncthreads();
        // S=4, distance 2, single barrier: writes hit stage (i+2)%4, reads i%4.

        uint32_t abase = sb + (i % S) * STAGE;
        uint32_t bbase = abase + ABYTES;

#pragma unroll
        for (int kk = 0; kk < 4; kk++) {
            int coff = (kk * 16 + kg) * 2;
            uint32_t a[MI][4], b[NT][4];
#pragma unroll
            for (int mi = 0; mi < MI; mi++) {
                int row = wm0 + mi * 16 + lrow8 + mg;
                uint32_t ad = abase + SMEM_SWIZZLE_128B((uint32_t)(row * 128 + coff));
                LDSM_X4(a[mi][0], a[mi][1], a[mi][2], a[mi][3], ad);
            }
#pragma unroll
            for (int nt = 0; nt < NT; nt++) {
                int row = wn0 + nt * 16 + lrow8 + mg;
                uint32_t bd = bbase + SMEM_SWIZZLE_128B((uint32_t)(row * 128 + coff));
                LDSM_X4(b[nt][0], b[nt][1], b[nt][2], b[nt][3], bd);
            }
#pragma unroll
            for (int mi = 0; mi < MI; mi++) {
#pragma unroll
                for (int nt = 0; nt < NT; nt++) {
                    if (FP16) {
                        MMA_F16(acc[mi][nt * 2 + 0], a[mi], b[nt][0], b[nt][2]);
                        MMA_F16(acc[mi][nt * 2 + 1], a[mi], b[nt][1], b[nt][3]);
                    } else {
                        MMA_BF16(acc[mi][nt * 2 + 0], a[mi], b[nt][0], b[nt][2]);
                        MMA_BF16(acc[mi][nt * 2 + 1], a[mi], b[nt][1], b[nt][3]);
                    }
                }
            }
        }
    }

    // ---------------- epilogue (registers only) ----------------
    int qrow = lane >> 2;
    int qcol = (lane & 3) * 2;
#pragma unroll
    for (int mi = 0; mi < MI; mi++) {
#pragma unroll
        for (int ni = 0; ni < NI; ni++) {
#pragma unroll
            for (int h = 0; h < 2; h++) {
#pragma unroll
                for (int q = 0; q < 2; q++) {
                    int m = m0 + wm0 + mi * 16 + qrow + h * 8;
                    int n = n0 + wn0 + ni * 8 + qcol + q;
                    float v = acc[mi][ni][h * 2 + q] + bias[n];
                    if (EPI == 0) {
                        Cf[(size_t)m * Nout + n] = v;
                    } else if (EPI == 1) {
                        v += __bfloat162float(rhi[(size_t)m * CC + n])
                           + __bfloat162float(rlo[(size_t)m * CC + n]);
                        split2h(v, Chi[(size_t)m * CC + n], Clo[(size_t)m * CC + n]);
                    } else {
                        float rs = rsqrtf(bn_rv[n] + 1e-5f);
                        v = (v - bn_rm[n]) * rs * bn_w[n] + bn_b[n];
                        v = fmaxf(v, 0.f);
                        int bb = m / LL, l = m - bb * LL;
                        Cf[((size_t)bb * CC + n) * LL + l] = v;
                    }
                }
            }
        }
    }
}

// ---------------- fused x_proj + dt (block per row, smem-staged) ----------------
__global__ void xproj_dt_kernel(const float* __restrict__ xpw,
                                const float* __restrict__ dtw)
{
    __shared__ float xrow[DD];
    __shared__ float xd[NPROJ];
    int m = blockIdx.x;
    int d = threadIdx.x;                 // 192 threads

    xrow[d] = g_xz[(size_t)m * DIN2 + d];
    __syncthreads();

    if (d < NPROJ) {
        const float* wr = xpw + d * DD;
        float acc = 0.f;
#pragma unroll 8
        for (int k = 0; k < DD; k++) acc += xrow[k] * wr[k];
        xd[d] = acc;
        g_xdbl[(size_t)m * NPROJ + d] = acc;
    }
    __syncthreads();

    float acc = 0.f;
#pragma unroll
    for (int r = 0; r < RR; r++) acc += xd[r] * dtw[d * RR + r];
    float sp = (acc > 20.f) ? acc : log1pf(__expf(acc));
    g_dts[(size_t)m * DD + d] = sp;
}

// ---------------- bidirectional scan: fwd+bwd concurrent, prefetched ----------------
__global__ void scan_kernel(const float* __restrict__ A_logs,
                            const float* __restrict__ Ds)
{
    __shared__ float sB[LL][NN];
    __shared__ float sC[LL][NN];
    int b = blockIdx.x & 63;
    bool back = blockIdx.x >= 64;
    int d = threadIdx.x;

    for (int i = d; i < LL * 2 * NN; i += LL) {
        int l = i >> 5, j = i & 31;
        float v = g_xdbl[((size_t)(b * LL + l)) * NPROJ + RR + j];
        if (j < NN) sB[l][j] = v;
        else        sC[l][j - NN] = v;
    }
    __syncthreads();

    float Ar[NN];
#pragma unroll
    for (int n = 0; n < NN; n++) Ar[n] = -expf(A_logs[d * NN + n]);
    float Dd = Ds[d];

    float u[NN];
#pragma unroll
    for (int n = 0; n < NN; n++) u[n] = 0.f;

    float* dst = back ? g_ssmb : g_ssmf;
    int l0   = back ? LL - 1 : 0;
    int step = back ? -1 : 1;

    int m = b * LL + l0;
    float dt = g_dts[(size_t)m * DD + d];
    float xv = g_xz [(size_t)m * DIN2 + d];
    for (int t = 0; t < LL; t++) {
        int l = l0 + t * step;
        float dtn = 0.f, xvn = 0.f;
        if (t + 1 < LL) {                       // prefetch next step
            int mn = b * LL + l + step;
            dtn = g_dts[(size_t)mn * DD + d];
            xvn = g_xz [(size_t)mn * DIN2 + d];
        }
        float y = 0.f;
#pragma unroll
        for (int n = 0; n < NN; n++) {
            float a = __expf(dt * Ar[n]);
            u[n] = a * u[n] + dt * sB[l][n] * xv;
            y += u[n] * sC[l][n];
        }
        dst[(size_t)(b * LL + l) * DD + d] = y + Dd * xv;
        dt = dtn; xv = xvn;
    }
}

// ---------------- gate: (fwd+bwd) * silu(z) -> hi/lo ssm (fp16) ----------------
__global__ void gate_kernel()
{
    int idx = blockIdx.x * blockDim.x + threadIdx.x;
    if (idx >= MM * DD) return;
    int m = idx / DD, d = idx % DD;
    float tot = g_ssmf[idx] + g_ssmb[idx];
    float z = g_xz[(size_t)m * DIN2 + DD + d];
    float sig = 1.f / (1.f + __expf(-z));
    split2h(tot * (z * sig), g_ssm_h[idx], g_ssm_l[idx]);
}

// ---------------- launch ----------------
extern "C" void kernel_launch(void* const* d_in, const int* in_sizes, int n_in,
                              void* d_out, int out_size)
{
    const float* feat_map = (const float*)d_in[0];
    const float* ln_w     = (const float*)d_in[1];
    const float* ln_b     = (const float*)d_in[2];
    const float* in_w     = (const float*)d_in[3];
    const float* in_b     = (const float*)d_in[4];
    const float* x_proj_w = (const float*)d_in[5];
    const float* dt_w     = (const float*)d_in[6];
    const float* A_logs   = (const float*)d_in[7];
    const float* Ds       = (const float*)d_in[8];
    const float* out_w    = (const float*)d_in[9];
    const float* out_b    = (const float*)d_in[10];
    const float* mo_w     = (const float*)d_in[11];
    const float* mo_b     = (const float*)d_in[12];
    const float* bn_w     = (const float*)d_in[13];
    const float* bn_b     = (const float*)d_in[14];
    const float* bn_rm    = (const float*)d_in[15];
    const float* bn_rv    = (const float*)d_in[16];
    float* out = (float*)d_out;

    __nv_bfloat16 *fm_h, *fm_l, *inw_e;
    __half *ssm_h, *ssm_l, *out1_h, *out1_l, *outw_h, *mow_h;
    float *xz;
    cudaGetSymbolAddress((void**)&fm_h,   g_fm_h);
    cudaGetSymbolAddress((void**)&fm_l,   g_fm_l);
    cudaGetSymbolAddress((void**)&ssm_h,  g_ssm_h);
    cudaGetSymbolAddress((void**)&ssm_l,  g_ssm_l);
    cudaGetSymbolAddress((void**)&out1_h, g_out1_h);
    cudaGetSymbolAddress((void**)&out1_l, g_out1_l);
    cudaGetSymbolAddress((void**)&inw_e,  g_inw_e);
    cudaGetSymbolAddress((void**)&outw_h, g_outw_h);
    cudaGetSymbolAddress((void**)&mow_h,  g_mow_h);
    cudaGetSymbolAddress((void**)&xz,     g_xz);

    const int SMEM_IN  = 4 * (128 + 128) * 128;   // 131072  (BM=128, BN=128)
    const int SMEM_BIG = 4 * (96 + 256) * 128;    // 180224  (BM=96,  BN=256)
    cudaFuncSetAttribute((gemm_mma<128, 128, 3, 0, 0>), cudaFuncAttributeMaxDynamicSharedMemorySize, SMEM_IN);
    cudaFuncSetAttribute((gemm_mma<96, 256, 2, 1, 1>),  cudaFuncAttributeMaxDynamicSharedMemorySize, SMEM_BIG);
    cudaFuncSetAttribute((gemm_mma<96, 256, 2, 1, 2>),  cudaFuncAttributeMaxDynamicSharedMemorySize, SMEM_BIG);

    // 1. transpose + LN -> fm hi/lo (bf16)
    ln_kernel<<<MM, 256>>>(feat_map, ln_w, ln_b);

    // weight conversions
    wconv_kernel<<<(DIN2 * CC + 255) / 256, 256>>>(in_w, inw_e, CC, DIN2 * CC);
    wconvh_kernel<<<(CC * DD + 255) / 256, 256>>>(out_w, outw_h, CC * DD);
    wconvh_kernel<<<(CC * CC + 255) / 256, 256>>>(mo_w, mow_h, CC * CC);

    // 2. in-projection (bf16-3): xz = fm @ in_w^T + in_b
    gemm_mma<128, 128, 3, 0, 0><<<dim3(DIN2 / 128, MM / 128), 256, SMEM_IN>>>(
        fm_h, fm_l, inw_e, CC, DIN2, in_b, nullptr, nullptr, xz, nullptr, nullptr,
        nullptr, nullptr, nullptr, nullptr);

    // 3. fused x-proj + dt
    xproj_dt_kernel<<<MM, DD>>>(x_proj_w, dt_w);

    // 4. scan (fwd+bwd concurrent, prefetched) + gate -> ssm hi/lo (fp16)
    scan_kernel<<<128, DD>>>(A_logs, Ds);
    gate_kernel<<<(MM * DD) / 256, 256>>>();

    // 5. out-projection (fp16-2, K'=2*192) + fm residual -> out1 hi/lo (fp16)
    gemm_mma<96, 256, 2, 1, 1><<<dim3(CC / 256, MM / 96), 256, SMEM_BIG>>>(
        (const __nv_bfloat16*)ssm_h, (const __nv_bfloat16*)ssm_l,
        (const __nv_bfloat16*)outw_h, DD, CC, out_b, fm_h, fm_l, nullptr,
        out1_h, out1_l, nullptr, nullptr, nullptr, nullptr);

    // 6. mixer GEMM (fp16-2, K'=2*2048) + BN + ReLU + NCHW write
    gemm_mma<96, 256, 2, 1, 2><<<dim3(CC / 256, MM / 96), 256, SMEM_BIG>>>(
        (const __nv_bfloat16*)out1_h, (const __nv_bfloat16*)out1_l,
        (const __nv_bfloat16*)mow_h, CC, CC, mo_b, nullptr, nullptr, out,
        nullptr, nullptr, bn_rm, bn_rv, bn_w, bn_b);
}

// round 17
// speedup vs baseline: 2.5753x; 1.0394x over previous
#include <cuda_runtime.h>
#include <cuda_bf16.h>
#include <cuda_fp16.h>
#include <cstdint>

// ---------------- problem constants ----------------
#define BSZ   64
#define CC    2048
#define LL    192
#define DIN2  384
#define DD    192
#define NN    16
#define RR    6
#define MM    (BSZ*LL)     // 12288
#define NPROJ 38

// ---------------- scratch ----------------
__device__ float g_xz  [(size_t)MM*DIN2];
__device__ float g_xdbl[(size_t)MM*NPROJ];
__device__ float g_dts [(size_t)MM*DD];
__device__ float g_ssmf[(size_t)MM*DD];
__device__ float g_ssmb[(size_t)MM*DD];
// fp16-2 activations (hi/lo)
__device__ __align__(128) __half g_fm_h  [(size_t)MM*CC];
__device__ __align__(128) __half g_fm_l  [(size_t)MM*CC];
__device__ __align__(128) __half g_ssm_h [(size_t)MM*DD];
__device__ __align__(128) __half g_ssm_l [(size_t)MM*DD];
__device__ __align__(128) __half g_out1_h[(size_t)MM*CC];
__device__ __align__(128) __half g_out1_l[(size_t)MM*CC];
// weights: plain fp16 (read for both K'-segments)
__device__ __align__(128) __half g_inw_h [(size_t)DIN2*CC];
__device__ __align__(128) __half g_outw_h[(size_t)CC*DD];
__device__ __align__(128) __half g_mow_h [(size_t)CC*CC];

// ---------------- helpers ----------------
__device__ __forceinline__ uint32_t smem_to_u32(const void* p) {
    uint32_t a;
    asm("{ .reg .u64 t; cvta.to.shared.u64 t, %1; cvt.u32.u64 %0, t; }" : "=r"(a) : "l"(p));
    return a;
}
#define SMEM_SWIZZLE_128B(off) ((off) ^ (((off) >> 3) & 0x70))

#define CP_ASYNC16(smem_u32, gptr) \
    asm volatile("cp.async.cg.shared.global [%0], [%1], 16;" \
                 :: "r"(smem_u32), "l"(__cvta_generic_to_global((const void*)(gptr))) : "memory")
#define CP_ASYNC_COMMIT() asm volatile("cp.async.commit_group;" ::: "memory")
#define CP_ASYNC_WAIT_2() asm volatile("cp.async.wait_group 2;" ::: "memory")

#define LDSM_X4(r0, r1, r2, r3, addr) \
    asm volatile("ldmatrix.sync.aligned.m8n8.x4.shared.b16 {%0,%1,%2,%3}, [%4];" \
                 : "=r"(r0), "=r"(r1), "=r"(r2), "=r"(r3) : "r"(addr))

#define MMA_F16(d, a, b0, b1) \
    asm volatile("mma.sync.aligned.m16n8k16.row.col.f32.f16.f16.f32 " \
                 "{%0,%1,%2,%3}, {%4,%5,%6,%7}, {%8,%9}, {%0,%1,%2,%3};" \
                 : "+f"((d)[0]), "+f"((d)[1]), "+f"((d)[2]), "+f"((d)[3]) \
                 : "r"((a)[0]), "r"((a)[1]), "r"((a)[2]), "r"((a)[3]), \
                   "r"(b0), "r"(b1))

// ---------------- split helpers ----------------
// fp16-2: A segs [hi, lo]; W single array read for both segs -> AhBh + AlBh
// (drops Ah*Bl ~ 2^-12 * coherence; measured ~2e-4 per GEMM chain)
__device__ __forceinline__ void split2h(float v, __half& h, __half& l) {
    h = __float2half_rn(v);
    l = __float2half_rn(v - __half2float(h));
}

// ---------------- 1. transpose + LayerNorm -> hi/lo fm (fp16) ----------------
__global__ void ln_kernel(const float* __restrict__ x,
                          const float* __restrict__ w,
                          const float* __restrict__ b)
{
    int m  = blockIdx.x;
    int bb = m / LL, l = m % LL;
    const float* src = x + (size_t)bb * CC * LL + l;

    float v[8];
    float s = 0.f, s2 = 0.f;
#pragma unroll
    for (int k = 0; k < 8; k++) {
        int c = threadIdx.x + k * 256;
        float t = src[(size_t)c * LL];
        v[k] = t; s += t; s2 += t * t;
    }
    __shared__ float sred[64];
#pragma unroll
    for (int o = 16; o > 0; o >>= 1) {
        s  += __shfl_down_sync(0xffffffffu, s,  o);
        s2 += __shfl_down_sync(0xffffffffu, s2, o);
    }
    int wid = threadIdx.x >> 5, lane = threadIdx.x & 31;
    if (lane == 0) { sred[wid] = s; sred[32 + wid] = s2; }
    __syncthreads();
    if (threadIdx.x == 0) {
        float a = 0.f, a2 = 0.f;
#pragma unroll
        for (int i = 0; i < 8; i++) { a += sred[i]; a2 += sred[32 + i]; }
        sred[0] = a; sred[32] = a2;
    }
    __syncthreads();
    s = sred[0]; s2 = sred[32];

    float mu   = s * (1.f / CC);
    float var  = s2 * (1.f / CC) - mu * mu;
    float rstd = rsqrtf(var + 1e-5f);

    __half* dh = g_fm_h + (size_t)m * CC;
    __half* dl = g_fm_l + (size_t)m * CC;
#pragma unroll
    for (int k = 0; k < 8; k++) {
        int c = threadIdx.x + k * 256;
        float fv = (v[k] - mu) * rstd * w[c] + b[c];
        split2h(fv, dh[c], dl[c]);
    }
}

// ---------------- weight conversion: fp32 -> fp16 ----------------
__global__ void wconvh_kernel(const float* __restrict__ w, __half* __restrict__ o, int total)
{
    int idx = blockIdx.x * blockDim.x + threadIdx.x;
    if (idx >= total) return;
    o[idx] = __float2half_rn(w[idx]);
}

// ---------------- fp16-2 mma.sync GEMM: C = A(M x 2K) * B(N x 2K)^T ----------------
// A segs [hi, lo] (two arrays, stride K); B single array read for BOTH segments.
// BM x BN block, BK=64, 4-stage cp.async (distance 2), single sync per iter,
// 8 warps (2m x 4n), ldmatrix fragments.
template <int BM, int BN, int EPI>
__global__ void __launch_bounds__(256) gemm_f16(
    const __half* __restrict__ Ahi, const __half* __restrict__ Alo,
    const __half* __restrict__ B,
    int K, int Nout,
    const float* __restrict__ bias,
    const __half* __restrict__ rhi, const __half* __restrict__ rlo,
    float* __restrict__ Cf,
    __half* __restrict__ Chi, __half* __restrict__ Clo,
    const float* __restrict__ bn_rm, const float* __restrict__ bn_rv,
    const float* __restrict__ bn_w,  const float* __restrict__ bn_b)
{
    constexpr int S      = 4;
    constexpr int ABYTES = BM * 128;
    constexpr int BBYTES = BN * 128;
    constexpr int STAGE  = ABYTES + BBYTES;
    constexpr int MI     = BM / 32;
    constexpr int NT     = BN / 64;
    constexpr int NI     = BN / 32;
    constexpr int AITER  = BM / 32;
    constexpr int BITER  = BN / 32;

    extern __shared__ char smem[];
    uint32_t sb = smem_to_u32(smem);

    int tid = threadIdx.x, wid = tid >> 5, lane = tid & 31;
    int m0 = blockIdx.y * BM, n0 = blockIdx.x * BN;
    int wm0 = (wid & 1) * (BM / 2);
    int wn0 = (wid >> 1) * (BN / 4);

    int lrow8 = lane & 7;
    int g     = lane >> 3;
    int mg    = (g & 1) * 8;
    int kg    = (g >> 1) * 8;

    float acc[MI][NI][4];
#pragma unroll
    for (int i = 0; i < MI; i++)
#pragma unroll
        for (int j = 0; j < NI; j++)
#pragma unroll
            for (int q = 0; q < 4; q++) acc[i][j][q] = 0.f;

    const int t3 = K >> 6;            // chunks per segment
    const int T  = 2 * t3;

    int lrow = tid >> 3;
    int lcol = tid & 7;
    auto load = [&](int j) {
        uint32_t abase = sb + (j % S) * STAGE;
        uint32_t bbase = abase + ABYTES;
        int s = j / t3;
        const __half* Ab = (s == 0) ? Ahi : Alo;
        int k0 = (j - s * t3) * 64;   // both segments read same B columns
#pragma unroll
        for (int c = 0; c < AITER; c++) {
            int row = lrow + c * 32;
            uint32_t soff = SMEM_SWIZZLE_128B((uint32_t)(row * 128 + lcol * 16));
            CP_ASYNC16(abase + soff, Ab + (size_t)(m0 + row) * K + k0 + lcol * 8);
        }
#pragma unroll
        for (int c = 0; c < BITER; c++) {
            int row = lrow + c * 32;
            uint32_t soff = SMEM_SWIZZLE_128B((uint32_t)(row * 128 + lcol * 16));
            CP_ASYNC16(bbase + soff, B + (size_t)(n0 + row) * K + k0 + lcol * 8);
        }
    };

    load(0); CP_ASYNC_COMMIT();
    load(1); CP_ASYNC_COMMIT();

    for (int i = 0; i < T; i++) {
        if (i + 2 < T) load(i + 2);
        CP_ASYNC_COMMIT();
        CP_ASYNC_WAIT_2();
        __syncthreads();
        // S=4, distance 2, single barrier: writes hit stage (i+2)%4, reads i%4.

        uint32_t abase = sb + (i % S) * STAGE;
        uint32_t bbase = abase + ABYTES;

#pragma unroll
        for (int kk = 0; kk < 4; kk++) {
            int coff = (kk * 16 + kg) * 2;
            uint32_t a[MI][4], b[NT][4];
#pragma unroll
            for (int mi = 0; mi < MI; mi++) {
                int row = wm0 + mi * 16 + lrow8 + mg;
                uint32_t ad = abase + SMEM_SWIZZLE_128B((uint32_t)(row * 128 + coff));
                LDSM_X4(a[mi][0], a[mi][1], a[mi][2], a[mi][3], ad);
            }
#pragma unroll
            for (int nt = 0; nt < NT; nt++) {
                int row = wn0 + nt * 16 + lrow8 + mg;
                uint32_t bd = bbase + SMEM_SWIZZLE_128B((uint32_t)(row * 128 + coff));
                LDSM_X4(b[nt][0], b[nt][1], b[nt][2], b[nt][3], bd);
            }
#pragma unroll
            for (int mi = 0; mi < MI; mi++) {
#pragma unroll
                for (int nt = 0; nt < NT; nt++) {
                    MMA_F16(acc[mi][nt * 2 + 0], a[mi], b[nt][0], b[nt][2]);
                    MMA_F16(acc[mi][nt * 2 + 1], a[mi], b[nt][1], b[nt][3]);
                }
            }
        }
    }

    // ---------------- epilogue (registers only) ----------------
    int qrow = lane >> 2;
    int qcol = (lane & 3) * 2;
#pragma unroll
    for (int mi = 0; mi < MI; mi++) {
#pragma unroll
        for (int ni = 0; ni < NI; ni++) {
#pragma unroll
            for (int h = 0; h < 2; h++) {
#pragma unroll
                for (int q = 0; q < 2; q++) {
                    int m = m0 + wm0 + mi * 16 + qrow + h * 8;
                    int n = n0 + wn0 + ni * 8 + qcol + q;
                    float v = acc[mi][ni][h * 2 + q] + bias[n];
                    if (EPI == 0) {
                        Cf[(size_t)m * Nout + n] = v;
                    } else if (EPI == 1) {
                        v += __half2float(rhi[(size_t)m * CC + n])
                           + __half2float(rlo[(size_t)m * CC + n]);
                        split2h(v, Chi[(size_t)m * CC + n], Clo[(size_t)m * CC + n]);
                    } else {
                        float rs = rsqrtf(bn_rv[n] + 1e-5f);
                        v = (v - bn_rm[n]) * rs * bn_w[n] + bn_b[n];
                        v = fmaxf(v, 0.f);
                        int bb = m / LL, l = m - bb * LL;
                        Cf[((size_t)bb * CC + n) * LL + l] = v;
                    }
                }
            }
        }
    }
}

// ---------------- fused x_proj + dt (block per row, smem-staged) ----------------
__global__ void xproj_dt_kernel(const float* __restrict__ xpw,
                                const float* __restrict__ dtw)
{
    __shared__ float xrow[DD];
    __shared__ float xd[NPROJ];
    int m = blockIdx.x;
    int d = threadIdx.x;                 // 192 threads

    xrow[d] = g_xz[(size_t)m * DIN2 + d];
    __syncthreads();

    if (d < NPROJ) {
        const float* wr = xpw + d * DD;
        float acc = 0.f;
#pragma unroll 8
        for (int k = 0; k < DD; k++) acc += xrow[k] * wr[k];
        xd[d] = acc;
        g_xdbl[(size_t)m * NPROJ + d] = acc;
    }
    __syncthreads();

    float acc = 0.f;
#pragma unroll
    for (int r = 0; r < RR; r++) acc += xd[r] * dtw[d * RR + r];
    float sp = (acc > 20.f) ? acc : log1pf(__expf(acc));
    g_dts[(size_t)m * DD + d] = sp;
}

// ---------------- bidirectional scan: fwd+bwd concurrent, prefetched ----------------
__global__ void scan_kernel(const float* __restrict__ A_logs,
                            const float* __restrict__ Ds)
{
    __shared__ float sB[LL][NN];
    __shared__ float sC[LL][NN];
    int b = blockIdx.x & 63;
    bool back = blockIdx.x >= 64;
    int d = threadIdx.x;

    for (int i = d; i < LL * 2 * NN; i += LL) {
        int l = i >> 5, j = i & 31;
        float v = g_xdbl[((size_t)(b * LL + l)) * NPROJ + RR + j];
        if (j < NN) sB[l][j] = v;
        else        sC[l][j - NN] = v;
    }
    __syncthreads();

    float Ar[NN];
#pragma unroll
    for (int n = 0; n < NN; n++) Ar[n] = -expf(A_logs[d * NN + n]);
    float Dd = Ds[d];

    float u[NN];
#pragma unroll
    for (int n = 0; n < NN; n++) u[n] = 0.f;

    float* dst = back ? g_ssmb : g_ssmf;
    int l0   = back ? LL - 1 : 0;
    int step = back ? -1 : 1;

    int m = b * LL + l0;
    float dt = g_dts[(size_t)m * DD + d];
    float xv = g_xz [(size_t)m * DIN2 + d];
    for (int t = 0; t < LL; t++) {
        int l = l0 + t * step;
        float dtn = 0.f, xvn = 0.f;
        if (t + 1 < LL) {
            int mn = b * LL + l + step;
            dtn = g_dts[(size_t)mn * DD + d];
            xvn = g_xz [(size_t)mn * DIN2 + d];
        }
        float y = 0.f;
#pragma unroll
        for (int n = 0; n < NN; n++) {
            float a = __expf(dt * Ar[n]);
            u[n] = a * u[n] + dt * sB[l][n] * xv;
            y += u[n] * sC[l][n];
        }
        dst[(size_t)(b * LL + l) * DD + d] = y + Dd * xv;
        dt = dtn; xv = xvn;
    }
}

// ---------------- gate: (fwd+bwd) * silu(z) -> hi/lo ssm (fp16) ----------------
__global__ void gate_kernel()
{
    int idx = blockIdx.x * blockDim.x + threadIdx.x;
    if (idx >= MM * DD) return;
    int m = idx / DD, d = idx % DD;
    float tot = g_ssmf[idx] + g_ssmb[idx];
    float z = g_xz[(size_t)m * DIN2 + DD + d];
    float sig = 1.f / (1.f + __expf(-z));
    split2h(tot * (z * sig), g_ssm_h[idx], g_ssm_l[idx]);
}

// ---------------- launch ----------------
extern "C" void kernel_launch(void* const* d_in, const int* in_sizes, int n_in,
                              void* d_out, int out_size)
{
    const float* feat_map = (const float*)d_in[0];
    const float* ln_w     = (const float*)d_in[1];
    const float* ln_b     = (const float*)d_in[2];
    const float* in_w     = (const float*)d_in[3];
    const float* in_b     = (const float*)d_in[4];
    const float* x_proj_w = (const float*)d_in[5];
    const float* dt_w     = (const float*)d_in[6];
    const float* A_logs   = (const float*)d_in[7];
    const float* Ds       = (const float*)d_in[8];
    const float* out_w    = (const float*)d_in[9];
    const float* out_b    = (const float*)d_in[10];
    const float* mo_w     = (const float*)d_in[11];
    const float* mo_b     = (const float*)d_in[12];
    const float* bn_w     = (const float*)d_in[13];
    const float* bn_b     = (const float*)d_in[14];
    const float* bn_rm    = (const float*)d_in[15];
    const float* bn_rv    = (const float*)d_in[16];
    float* out = (float*)d_out;

    __half *fm_h, *fm_l, *ssm_h, *ssm_l, *out1_h, *out1_l;
    __half *inw_h, *outw_h, *mow_h;
    float *xz;
    cudaGetSymbolAddress((void**)&fm_h,   g_fm_h);
    cudaGetSymbolAddress((void**)&fm_l,   g_fm_l);
    cudaGetSymbolAddress((void**)&ssm_h,  g_ssm_h);
    cudaGetSymbolAddress((void**)&ssm_l,  g_ssm_l);
    cudaGetSymbolAddress((void**)&out1_h, g_out1_h);
    cudaGetSymbolAddress((void**)&out1_l, g_out1_l);
    cudaGetSymbolAddress((void**)&inw_h,  g_inw_h);
    cudaGetSymbolAddress((void**)&outw_h, g_outw_h);
    cudaGetSymbolAddress((void**)&mow_h,  g_mow_h);
    cudaGetSymbolAddress((void**)&xz,     g_xz);

    const int SMEM_IN  = 4 * (128 + 128) * 128;   // 131072  (BM=128, BN=128)
    const int SMEM_BIG = 4 * (96 + 256) * 128;    // 180224  (BM=96,  BN=256)
    cudaFuncSetAttribute((gemm_f16<128, 128, 0>), cudaFuncAttributeMaxDynamicSharedMemorySize, SMEM_IN);
    cudaFuncSetAttribute((gemm_f16<96, 256, 1>),  cudaFuncAttributeMaxDynamicSharedMemorySize, SMEM_BIG);
    cudaFuncSetAttribute((gemm_f16<96, 256, 2>),  cudaFuncAttributeMaxDynamicSharedMemorySize, SMEM_BIG);

    // 1. transpose + LN -> fm hi/lo (fp16)
    ln_kernel<<<MM, 256>>>(feat_map, ln_w, ln_b);

    // weight conversions (plain fp16)
    wconvh_kernel<<<(DIN2 * CC + 255) / 256, 256>>>(in_w, inw_h, DIN2 * CC);
    wconvh_kernel<<<(CC * DD + 255) / 256, 256>>>(out_w, outw_h, CC * DD);
    wconvh_kernel<<<(CC * CC + 255) / 256, 256>>>(mo_w, mow_h, CC * CC);

    // 2. in-projection (fp16-2, K'=2*2048): xz = fm @ in_w^T + in_b
    gemm_f16<128, 128, 0><<<dim3(DIN2 / 128, MM / 128), 256, SMEM_IN>>>(
        fm_h, fm_l, inw_h, CC, DIN2, in_b, nullptr, nullptr, xz, nullptr, nullptr,
        nullptr, nullptr, nullptr, nullptr);

    // 3. fused x-proj + dt
    xproj_dt_kernel<<<MM, DD>>>(x_proj_w, dt_w);

    // 4. scan (fwd+bwd concurrent, prefetched) + gate -> ssm hi/lo (fp16)
    scan_kernel<<<128, DD>>>(A_logs, Ds);
    gate_kernel<<<(MM * DD) / 256, 256>>>();

    // 5. out-projection (fp16-2, K'=2*192) + fm residual -> out1 hi/lo (fp16)
    gemm_f16<96, 256, 1><<<dim3(CC / 256, MM / 96), 256, SMEM_BIG>>>(
        ssm_h, ssm_l, outw_h, DD, CC, out_b, fm_h, fm_l, nullptr,
        out1_h, out1_l, nullptr, nullptr, nullptr, nullptr);

    // 6. mixer GEMM (fp16-2, K'=2*2048) + BN + ReLU + NCHW write
    gemm_f16<96, 256, 2><<<dim3(CC / 256, MM / 96), 256, SMEM_BIG>>>(
        out1_h, out1_l, mow_h, CC, CC, mo_b, nullptr, nullptr, out,
        nullptr, nullptr, bn_rm, bn_rv, bn_w, bn_b);
}